// round 11
// baseline (speedup 1.0000x reference)
#include <cuda_runtime.h>
#include <cuda_fp16.h>
#include <math.h>
#include <cstdint>

// Problem constants
#define B_    4
#define LQ    4096
#define CC    768
#define NHH   12
#define DH    64
#define HH    64
#define WW    64
#define HID   192
#define MROWS (B_*LQ)   // 16384

// ---------------- scratch ----------------
__device__ __align__(16) __half g_xf[MROWS*CC];                     // LN(feat) fp16
__device__ __align__(16) __half g_xq[MROWS*CC];                     // LN(query) fp16
__device__ __align__(16) __half g_value[MROWS*CC];                  // value fp16
__device__ __align__(16) float  g_offatt[MROWS*192];                // off(96)+logits(48)+pad
__device__ __align__(16) __half g_s[MROWS*CC];                      // sampled fp16
__device__ __align__(16) __half g_hmid[MROWS*HID];                  // FFN hidden fp16
// transposed weights [Npad][K] fp16
__device__ __align__(16) __half g_wvt[CC*CC];
__device__ __align__(16) __half g_wot[CC*CC];
__device__ __align__(16) __half g_wct[256*CC];
__device__ __align__(16) __half g_w1t[256*CC];
__device__ __align__(16) __half g_w2t[CC*HID];
__device__ float g_bcomb[256], g_b1p[256];

// ---------------- vectorized LN body ----------------
__device__ __forceinline__ void ln_row(const float* __restrict__ in,
                                       const float* __restrict__ gamma,
                                       const float* __restrict__ beta,
                                       __half* __restrict__ oh, int row)
{
    int t = threadIdx.x;
    float4 v = make_float4(0.f, 0.f, 0.f, 0.f);
    if (t < 192) v = *reinterpret_cast<const float4*>(in + (size_t)row * CC + t * 4);
    float s  = v.x + v.y + v.z + v.w;
    float s2 = v.x*v.x + v.y*v.y + v.z*v.z + v.w*v.w;
    #pragma unroll
    for (int o = 16; o; o >>= 1) {
        s  += __shfl_xor_sync(0xffffffffu, s,  o);
        s2 += __shfl_xor_sync(0xffffffffu, s2, o);
    }
    __shared__ float ssum[8], ssum2[8];
    int w = t >> 5;
    if ((t & 31) == 0) { ssum[w] = s; ssum2[w] = s2; }
    __syncthreads();
    float S = 0.f, S2 = 0.f;
    #pragma unroll
    for (int i = 0; i < 8; i++) { S += ssum[i]; S2 += ssum2[i]; }
    float mean = S * (1.0f / CC);
    float var  = S2 * (1.0f / CC) - mean * mean;
    float inv  = rsqrtf(var + 1e-5f);
    if (t < 192) {
        float4 gg = *reinterpret_cast<const float4*>(gamma + t * 4);
        float4 bb = *reinterpret_cast<const float4*>(beta  + t * 4);
        __half2 h0 = __floats2half2_rn((v.x - mean) * inv * gg.x + bb.x,
                                       (v.y - mean) * inv * gg.y + bb.y);
        __half2 h1 = __floats2half2_rn((v.z - mean) * inv * gg.z + bb.z,
                                       (v.w - mean) * inv * gg.w + bb.w);
        *reinterpret_cast<__half2*>(oh + (size_t)row * CC + t * 4)     = h0;
        *reinterpret_cast<__half2*>(oh + (size_t)row * CC + t * 4 + 2) = h1;
    }
}

// ---------------- fused prep: weight transpose + both LNs ----------------
__global__ __launch_bounds__(256) void prep_kernel(
    const float* __restrict__ feat, const float* __restrict__ query,
    const float* __restrict__ fn_g, const float* __restrict__ fn_b,
    const float* __restrict__ qn_g, const float* __restrict__ qn_b,
    __half* __restrict__ xf, __half* __restrict__ xq,
    const float* Wv, const float* Wout, const float* Woff, const float* Watt,
    const float* W1, const float* W2,
    __half* wvt, __half* wot, __half* wct, __half* w1t, __half* w2t,
    const float* boff, const float* batt, const float* b1,
    float* bcomb, float* b1p)
{
    int blk = blockIdx.x;
    if (blk >= 6721) {
        int row = blk - 6721;
        if (row < MROWS) ln_row(feat, fn_g, fn_b, xf, row);
        else             ln_row(query, qn_g, qn_b, xq, row - MROWS);
        return;
    }
    const float* src; __half* dst; int K, N, Npad, rel;
    if (blk < 2304)      { src=Wv;   dst=wvt;        K=CC;  N=CC;  Npad=CC;  rel=blk; }
    else if (blk < 4608) { src=Wout; dst=wot;        K=CC;  N=CC;  Npad=CC;  rel=blk-2304; }
    else if (blk < 4896) { src=Woff; dst=wct;        K=CC;  N=96;  Npad=96;  rel=blk-4608; }
    else if (blk < 5376) { src=Watt; dst=wct+96*CC;  K=CC;  N=48;  Npad=160; rel=blk-4896; }
    else if (blk < 6144) { src=W1;   dst=w1t;        K=CC;  N=HID; Npad=256; rel=blk-5376; }
    else if (blk < 6720) { src=W2;   dst=w2t;        K=HID; N=CC;  Npad=CC;  rel=blk-6144; }
    else {
        int i = threadIdx.x;
        bcomb[i] = (i < 96) ? boff[i] : (i < 144 ? batt[i - 96] : 0.0f);
        b1p[i]   = (i < 192) ? b1[i] : 0.0f;
        return;
    }
    int idx = rel * 256 + threadIdx.x;
    if (idx >= Npad * K) return;
    int n = idx / K, k = idx - n * K;
    float v = (n < N) ? src[(size_t)k * N + n] : 0.0f;
    dst[idx] = __float2half(v);
}

__global__ __launch_bounds__(256) void ln_kernel(const float* __restrict__ in,
                                                 const float* __restrict__ gamma,
                                                 const float* __restrict__ beta,
                                                 __half* __restrict__ oh)
{
    ln_row(in, gamma, beta, oh, blockIdx.x);
}

// ---------------- GEMM core: BK=32, 3-stage, 3 CTAs/SM ----------------
#define SSTR 40  // smem row stride in halfs (32 + 8 pad)

__device__ __forceinline__ void mma16816(float* d, const uint32_t* a, const uint32_t* b) {
    asm volatile(
        "mma.sync.aligned.m16n8k16.row.col.f32.f16.f16.f32 "
        "{%0,%1,%2,%3}, {%4,%5,%6,%7}, {%8,%9}, {%0,%1,%2,%3};"
        : "+f"(d[0]), "+f"(d[1]), "+f"(d[2]), "+f"(d[3])
        : "r"(a[0]), "r"(a[1]), "r"(a[2]), "r"(a[3]), "r"(b[0]), "r"(b[1]));
}
#define LDSM_X4(R0,R1,R2,R3,ADDR) \
    asm volatile("ldmatrix.sync.aligned.m8n8.x4.shared.b16 {%0,%1,%2,%3}, [%4];" \
        : "=r"(R0), "=r"(R1), "=r"(R2), "=r"(R3) : "r"(ADDR))
#define CPA16(DST,SRC) \
    asm volatile("cp.async.cg.shared.global [%0], [%1], 16;" :: "r"(DST), "l"(SRC) : "memory")
#define CPC() asm volatile("cp.async.commit_group;" ::: "memory")
#define CPW1() asm volatile("cp.async.wait_group 1;" ::: "memory")
#define CPW0() asm volatile("cp.async.wait_group 0;" ::: "memory")

// EPI: 0 bias->fp32; 1 bias+res->fp32; 2 bias+GELU->fp16; 3 bias->fp16
template<int EPI>
__device__ __forceinline__ void gemm_body(
    const __half* __restrict__ A, const __half* __restrict__ B,
    const float* __restrict__ bias, const float* __restrict__ res,
    float* __restrict__ Cf, __half* __restrict__ Ch,
    int K, int ldc, int Ncols, int m0, int n0, __half* sm)
{
    const int ARR = 128 * SSTR;        // halves per array
    const int STG = 2 * ARR;           // stage: A, B

    const int tid = threadIdx.x, lane = tid & 31, wid = tid >> 5;
    const int wm = wid & 1, wn = wid >> 1;

    const uint32_t smb = (uint32_t)__cvta_generic_to_shared(sm);

    // staging: per array 128 rows x 32 halfs = 512 x 16B, 256 thr, 2 iters
    int srow[2], sg[2];
    #pragma unroll
    for (int i = 0; i < 2; i++) { int idx = i * 256 + tid; srow[i] = idx >> 2; sg[i] = idx & 3; }

    auto issue = [&](int c, int s) {
        const int kc = c * 32;
        #pragma unroll
        for (int i = 0; i < 2; i++) {
            int row = srow[i], g = sg[i];
            size_t ga = (size_t)(m0 + row) * K + kc + g * 8;
            size_t gb = (size_t)(n0 + row) * K + kc + g * 8;
            uint32_t so = smb + (uint32_t)(s * STG + row * SSTR + g * 8) * 2;
            CPA16(so + 0 * ARR * 2, A + ga);
            CPA16(so + 1 * ARR * 2, B + gb);
        }
    };

    float acc[4][4][4];
    #pragma unroll
    for (int i = 0; i < 4; i++)
        #pragma unroll
        for (int j = 0; j < 4; j++)
            #pragma unroll
            for (int q = 0; q < 4; q++) acc[i][j][q] = 0.f;

    const int a_lrow = lane & 15, a_lcol = (lane >> 4) * 8;
    const int b_lrow = (lane & 7) + ((lane >> 4) * 8), b_lcol = ((lane >> 3) & 1) * 8;

    const int KC = K >> 5;   // >= 6 always
    issue(0, 0); CPC();
    issue(1, 1); CPC();

    for (int c = 0; c < KC; c++) {
        if (c == KC - 1) { CPW0(); } else { CPW1(); }
        __syncthreads();
        if (c + 2 < KC) { issue(c + 2, (c + 2) % 3); CPC(); }

        const int st = (c % 3) * STG;
        const uint32_t baseA = smb + (uint32_t)(st + 0 * ARR) * 2;
        const uint32_t baseB = smb + (uint32_t)(st + 1 * ARR) * 2;

        #pragma unroll
        for (int kk = 0; kk < 2; kk++) {
            const int kb = kk * 16;
            uint32_t bf[4][2];
            #pragma unroll
            for (int nn = 0; nn < 2; nn++) {
                uint32_t off = (uint32_t)((wn * 32 + nn * 16 + b_lrow) * SSTR + kb + b_lcol) * 2;
                LDSM_X4(bf[nn*2][0], bf[nn*2][1], bf[nn*2+1][0], bf[nn*2+1][1], baseB + off);
            }
            #pragma unroll
            for (int mi = 0; mi < 4; mi++) {
                uint32_t off = (uint32_t)((wm * 64 + mi * 16 + a_lrow) * SSTR + kb + a_lcol) * 2;
                uint32_t ah[4];
                LDSM_X4(ah[0], ah[1], ah[2], ah[3], baseA + off);
                #pragma unroll
                for (int ni = 0; ni < 4; ni++)
                    mma16816(acc[mi][ni], ah, bf[ni]);
            }
        }
    }

    const int qrow = lane >> 2, qk = (lane & 3) * 2;
    #pragma unroll
    for (int mi = 0; mi < 4; mi++) {
        #pragma unroll
        for (int ni = 0; ni < 4; ni++) {
            int c0 = n0 + wn * 32 + ni * 8 + qk;
            if (c0 >= Ncols) continue;
            int r0 = m0 + wm * 64 + mi * 16 + qrow;
            float b0 = bias[c0], b1v = bias[c0 + 1];
            #pragma unroll
            for (int h = 0; h < 2; h++) {
                int m = r0 + h * 8;
                float v0 = acc[mi][ni][h*2+0] + b0;
                float v1 = acc[mi][ni][h*2+1] + b1v;
                if (EPI == 1) {
                    float2 rr = *reinterpret_cast<const float2*>(res + (size_t)m * ldc + c0);
                    v0 += rr.x; v1 += rr.y;
                }
                if (EPI == 2) {
                    v0 = 0.5f * v0 * (1.0f + erff(v0 * 0.70710678118654752f));
                    v1 = 0.5f * v1 * (1.0f + erff(v1 * 0.70710678118654752f));
                }
                if (EPI == 2 || EPI == 3) {
                    *reinterpret_cast<__half2*>(Ch + (size_t)m * ldc + c0) =
                        __floats2half2_rn(v0, v1);
                } else {
                    *reinterpret_cast<float2*>(Cf + (size_t)m * ldc + c0) =
                        make_float2(v0, v1);
                }
            }
        }
    }
}

template<int EPI>
__global__ __launch_bounds__(256, 3) void mma_gemm(
    const __half* __restrict__ A, const __half* __restrict__ B,
    const float* __restrict__ bias, const float* __restrict__ res,
    float* __restrict__ Cf, __half* __restrict__ Ch,
    int K, int ldc, int Ncols)
{
    extern __shared__ __half sm[];
    gemm_body<EPI>(A, B, bias, res, Cf, Ch, K, ldc, Ncols,
                   blockIdx.y * 128, blockIdx.x * 128, sm);
}

// fused pair: value GEMM (768 CTAs) + offset/attention GEMM (256 CTAs)
__global__ __launch_bounds__(256, 3) void gemm_pair_kernel(
    const __half* __restrict__ xf, const __half* __restrict__ wvt,
    const float* __restrict__ bv, __half* __restrict__ val,
    const __half* __restrict__ xq, const __half* __restrict__ wct,
    const float* __restrict__ bcomb, float* __restrict__ offatt)
{
    extern __shared__ __half sm[];
    int t = blockIdx.x;
    if (t < 768) {
        gemm_body<3>(xf, wvt, bv, nullptr, nullptr, val,
                     CC, CC, CC, (t / 6) * 128, (t % 6) * 128, sm);
    } else {
        int t2 = t - 768;
        gemm_body<0>(xq, wct, bcomb, nullptr, offatt, nullptr,
                     CC, 192, 144, (t2 / 2) * 128, (t2 % 2) * 128, sm);
    }
}

// ---------------- sampling: softmax(4) + bilinear -> fp16 ----------------
__global__ __launch_bounds__(256) void sample_kernel(
    const __half* __restrict__ value,
    const float* __restrict__ refp,
    const float* __restrict__ offatt,
    __half* __restrict__ oh)
{
    int gid = blockIdx.x * 4 + (threadIdx.x >> 6);
    int di  = threadIdx.x & 63;
    int head = gid % NHH;
    int bq   = gid / NHH;
    int b    = bq / LQ;

    const float* rp = refp + (size_t)bq * 2;
    float rx = rp[0], ry = rp[1];
    const float* op = offatt + (size_t)bq * 192 + head * 8;
    const float* lp = offatt + (size_t)bq * 192 + 96 + head * 4;

    float l0 = lp[0], l1 = lp[1], l2 = lp[2], l3 = lp[3];
    float mx = fmaxf(fmaxf(l0, l1), fmaxf(l2, l3));
    float e0 = expf(l0 - mx), e1 = expf(l1 - mx), e2 = expf(l2 - mx), e3 = expf(l3 - mx);
    float inv = 1.0f / (e0 + e1 + e2 + e3);
    float wsm[4] = {e0 * inv, e1 * inv, e2 * inv, e3 * inv};

    const __half* vb = value + (size_t)b * (HH * WW) * CC + head * DH + di;
    float acc = 0.f;
    #pragma unroll
    for (int p = 0; p < 4; p++) {
        float x = rx * (float)WW + op[p*2+0] - 0.5f;
        float y = ry * (float)HH + op[p*2+1] - 0.5f;
        float x0f = floorf(x), y0f = floorf(y);
        int   x0 = (int)x0f,  y0 = (int)y0f;
        float wx1 = x - x0f, wy1 = y - y0f;
        float wx0 = 1.f - wx1, wy0 = 1.f - wy1;
        float s = 0.f;
        #pragma unroll
        for (int cc = 0; cc < 4; cc++) {
            int xi = x0 + (cc & 1);
            int yi = y0 + (cc >> 1);
            float w = ((cc & 1) ? wx1 : wx0) * ((cc >> 1) ? wy1 : wy0);
            if (xi >= 0 && xi < WW && yi >= 0 && yi < HH)
                s += w * __half2float(vb[(size_t)(yi * WW + xi) * CC]);
        }
        acc += wsm[p] * s;
    }
    oh[(size_t)bq * CC + head * DH + di] = __float2half(acc);
}

// ---------------- launch ----------------
extern "C" void kernel_launch(void* const* d_in, const int* in_sizes, int n_in,
                              void* d_out, int out_size)
{
    const float* query = (const float*)d_in[0];
    const float* refp  = (const float*)d_in[1];
    const float* feat  = (const float*)d_in[2];
    int p = n_in - 18;
    const float* qn_g  = (const float*)d_in[p + 0];
    const float* qn_b  = (const float*)d_in[p + 1];
    const float* fn_g  = (const float*)d_in[p + 2];
    const float* fn_b  = (const float*)d_in[p + 3];
    const float* Wv    = (const float*)d_in[p + 4];
    const float* bv    = (const float*)d_in[p + 5];
    const float* Woff  = (const float*)d_in[p + 6];
    const float* boff  = (const float*)d_in[p + 7];
    const float* Watt  = (const float*)d_in[p + 8];
    const float* batt  = (const float*)d_in[p + 9];
    const float* Wout  = (const float*)d_in[p + 10];
    const float* bout  = (const float*)d_in[p + 11];
    const float* ffn_g = (const float*)d_in[p + 12];
    const float* ffn_b = (const float*)d_in[p + 13];
    const float* W1    = (const float*)d_in[p + 14];
    const float* b1    = (const float*)d_in[p + 15];
    const float* W2    = (const float*)d_in[p + 16];
    const float* b2    = (const float*)d_in[p + 17];
    float* out = (float*)d_out;

    __half *xf, *xq, *val, *s, *hmid;
    __half *wvt, *wot, *wct, *w1t, *w2t;
    float *offatt, *bcomb, *b1p;
    cudaGetSymbolAddress((void**)&xf, g_xf);
    cudaGetSymbolAddress((void**)&xq, g_xq);
    cudaGetSymbolAddress((void**)&val, g_value);
    cudaGetSymbolAddress((void**)&s, g_s);
    cudaGetSymbolAddress((void**)&hmid, g_hmid);
    cudaGetSymbolAddress((void**)&wvt, g_wvt);
    cudaGetSymbolAddress((void**)&wot, g_wot);
    cudaGetSymbolAddress((void**)&wct, g_wct);
    cudaGetSymbolAddress((void**)&w1t, g_w1t);
    cudaGetSymbolAddress((void**)&w2t, g_w2t);
    cudaGetSymbolAddress((void**)&offatt, g_offatt);
    cudaGetSymbolAddress((void**)&bcomb, g_bcomb);
    cudaGetSymbolAddress((void**)&b1p, g_b1p);

    const int SMEM_GEMM = 3 * 2 * 128 * SSTR * 2;   // 61440 B -> 3 CTAs/SM
    cudaFuncSetAttribute(mma_gemm<1>, cudaFuncAttributeMaxDynamicSharedMemorySize, SMEM_GEMM);
    cudaFuncSetAttribute(mma_gemm<2>, cudaFuncAttributeMaxDynamicSharedMemorySize, SMEM_GEMM);
    cudaFuncSetAttribute(gemm_pair_kernel, cudaFuncAttributeMaxDynamicSharedMemorySize, SMEM_GEMM);

    // 1. fused prep: weight transpose + LN(feat) + LN(query)
    prep_kernel<<<6721 + 2 * MROWS, 256>>>(feat, query, fn_g, fn_b, qn_g, qn_b, xf, xq,
        Wv, Wout, Woff, Watt, W1, W2, wvt, wot, wct, w1t, w2t,
        boff, batt, b1, bcomb, b1p);

    // 2. fused GEMM pair: value + offsets/logits
    gemm_pair_kernel<<<1024, 256, SMEM_GEMM>>>(xf, wvt, bv, val, xq, wct, bcomb, offatt);

    // 3. softmax + bilinear sampling -> fp16
    sample_kernel<<<MROWS * NHH / 4, 256>>>(val, refp, offatt, s);

    // 4. out = query + samp @ Wout + bout
    mma_gemm<1><<<dim3(6, 128), 256, SMEM_GEMM>>>(s, wot, bout, query,
        out, nullptr, CC, CC, CC);

    // 5. FFN
    ln_kernel<<<MROWS, 256>>>(out, ffn_g, ffn_b, xf);
    mma_gemm<2><<<dim3(2, 128), 256, SMEM_GEMM>>>(xf, w1t, b1p, nullptr,
        nullptr, hmid, CC, HID, HID);
    mma_gemm<1><<<dim3(6, 128), 256, SMEM_GEMM>>>(hmid, w2t, b2, out,
        out, nullptr, HID, CC, CC);
}

// round 12
// speedup vs baseline: 1.5173x; 1.5173x over previous
#include <cuda_runtime.h>
#include <cuda_fp16.h>
#include <math.h>
#include <cstdint>

// Problem constants
#define B_    4
#define LQ    4096
#define CC    768
#define NHH   12
#define DH    64
#define HH    64
#define WW    64
#define HID   192
#define MROWS (B_*LQ)   // 16384

// ---------------- scratch ----------------
__device__ __align__(16) __half g_xf[MROWS*CC];                     // LN(feat) fp16
__device__ __align__(16) __half g_xq[MROWS*CC];                     // LN(query) fp16
__device__ __align__(16) __half g_value[MROWS*CC];                  // value fp16
__device__ __align__(16) float  g_offatt[MROWS*192];                // off(96)+logits(48)+pad
__device__ __align__(16) __half g_s[MROWS*CC];                      // sampled fp16
__device__ __align__(16) __half g_hmid[MROWS*HID];                  // FFN hidden fp16
// transposed weights [Npad][K] fp16
__device__ __align__(16) __half g_wvt[CC*CC];
__device__ __align__(16) __half g_wot[CC*CC];
__device__ __align__(16) __half g_wct[256*CC];
__device__ __align__(16) __half g_w1t[256*CC];
__device__ __align__(16) __half g_w2t[CC*HID];
__device__ float g_bcomb[256], g_b1p[256];

// ---------------- vectorized LN body ----------------
__device__ __forceinline__ void ln_row(const float* __restrict__ in,
                                       const float* __restrict__ gamma,
                                       const float* __restrict__ beta,
                                       __half* __restrict__ oh, int row)
{
    int t = threadIdx.x;
    float4 v = make_float4(0.f, 0.f, 0.f, 0.f);
    if (t < 192) v = *reinterpret_cast<const float4*>(in + (size_t)row * CC + t * 4);
    float s  = v.x + v.y + v.z + v.w;
    float s2 = v.x*v.x + v.y*v.y + v.z*v.z + v.w*v.w;
    #pragma unroll
    for (int o = 16; o; o >>= 1) {
        s  += __shfl_xor_sync(0xffffffffu, s,  o);
        s2 += __shfl_xor_sync(0xffffffffu, s2, o);
    }
    __shared__ float ssum[8], ssum2[8];
    int w = t >> 5;
    if ((t & 31) == 0) { ssum[w] = s; ssum2[w] = s2; }
    __syncthreads();
    float S = 0.f, S2 = 0.f;
    #pragma unroll
    for (int i = 0; i < 8; i++) { S += ssum[i]; S2 += ssum2[i]; }
    float mean = S * (1.0f / CC);
    float var  = S2 * (1.0f / CC) - mean * mean;
    float inv  = rsqrtf(var + 1e-5f);
    if (t < 192) {
        float4 gg = *reinterpret_cast<const float4*>(gamma + t * 4);
        float4 bb = *reinterpret_cast<const float4*>(beta  + t * 4);
        __half2 h0 = __floats2half2_rn((v.x - mean) * inv * gg.x + bb.x,
                                       (v.y - mean) * inv * gg.y + bb.y);
        __half2 h1 = __floats2half2_rn((v.z - mean) * inv * gg.z + bb.z,
                                       (v.w - mean) * inv * gg.w + bb.w);
        *reinterpret_cast<__half2*>(oh + (size_t)row * CC + t * 4)     = h0;
        *reinterpret_cast<__half2*>(oh + (size_t)row * CC + t * 4 + 2) = h1;
    }
}

// ---------------- fused prep: weight transpose + both LNs ----------------
__global__ __launch_bounds__(256) void prep_kernel(
    const float* __restrict__ feat, const float* __restrict__ query,
    const float* __restrict__ fn_g, const float* __restrict__ fn_b,
    const float* __restrict__ qn_g, const float* __restrict__ qn_b,
    __half* __restrict__ xf, __half* __restrict__ xq,
    const float* Wv, const float* Wout, const float* Woff, const float* Watt,
    const float* W1, const float* W2,
    __half* wvt, __half* wot, __half* wct, __half* w1t, __half* w2t,
    const float* boff, const float* batt, const float* b1,
    float* bcomb, float* b1p)
{
    int blk = blockIdx.x;
    if (blk >= 6721) {
        int row = blk - 6721;
        if (row < MROWS) ln_row(feat, fn_g, fn_b, xf, row);
        else             ln_row(query, qn_g, qn_b, xq, row - MROWS);
        return;
    }
    const float* src; __half* dst; int K, N, Npad, rel;
    if (blk < 2304)      { src=Wv;   dst=wvt;        K=CC;  N=CC;  Npad=CC;  rel=blk; }
    else if (blk < 4608) { src=Wout; dst=wot;        K=CC;  N=CC;  Npad=CC;  rel=blk-2304; }
    else if (blk < 4896) { src=Woff; dst=wct;        K=CC;  N=96;  Npad=96;  rel=blk-4608; }
    else if (blk < 5376) { src=Watt; dst=wct+96*CC;  K=CC;  N=48;  Npad=160; rel=blk-4896; }
    else if (blk < 6144) { src=W1;   dst=w1t;        K=CC;  N=HID; Npad=256; rel=blk-5376; }
    else if (blk < 6720) { src=W2;   dst=w2t;        K=HID; N=CC;  Npad=CC;  rel=blk-6144; }
    else {
        int i = threadIdx.x;
        bcomb[i] = (i < 96) ? boff[i] : (i < 144 ? batt[i - 96] : 0.0f);
        b1p[i]   = (i < 192) ? b1[i] : 0.0f;
        return;
    }
    int idx = rel * 256 + threadIdx.x;
    if (idx >= Npad * K) return;
    int n = idx / K, k = idx - n * K;
    float v = (n < N) ? src[(size_t)k * N + n] : 0.0f;
    dst[idx] = __float2half(v);
}

__global__ __launch_bounds__(256) void ln_kernel(const float* __restrict__ in,
                                                 const float* __restrict__ gamma,
                                                 const float* __restrict__ beta,
                                                 __half* __restrict__ oh)
{
    ln_row(in, gamma, beta, oh, blockIdx.x);
}

// ---------------- GEMM core: BK=64, 2-stage, 3 CTAs/SM ----------------
#define SSTR 72  // smem row stride in halfs (64 + 8 pad)

__device__ __forceinline__ void mma16816(float* d, const uint32_t* a, const uint32_t* b) {
    asm volatile(
        "mma.sync.aligned.m16n8k16.row.col.f32.f16.f16.f32 "
        "{%0,%1,%2,%3}, {%4,%5,%6,%7}, {%8,%9}, {%0,%1,%2,%3};"
        : "+f"(d[0]), "+f"(d[1]), "+f"(d[2]), "+f"(d[3])
        : "r"(a[0]), "r"(a[1]), "r"(a[2]), "r"(a[3]), "r"(b[0]), "r"(b[1]));
}
#define LDSM_X4(R0,R1,R2,R3,ADDR) \
    asm volatile("ldmatrix.sync.aligned.m8n8.x4.shared.b16 {%0,%1,%2,%3}, [%4];" \
        : "=r"(R0), "=r"(R1), "=r"(R2), "=r"(R3) : "r"(ADDR))
#define CPA16(DST,SRC) \
    asm volatile("cp.async.cg.shared.global [%0], [%1], 16;" :: "r"(DST), "l"(SRC) : "memory")
#define CPC() asm volatile("cp.async.commit_group;" ::: "memory")
#define CPW0() asm volatile("cp.async.wait_group 0;" ::: "memory")

// EPI: 0 bias->fp32; 1 bias+res->fp32; 2 bias+GELU->fp16; 3 bias->fp16
template<int EPI>
__device__ __forceinline__ void gemm_body(
    const __half* __restrict__ A, const __half* __restrict__ B,
    const float* __restrict__ bias, const float* __restrict__ res,
    float* __restrict__ Cf, __half* __restrict__ Ch,
    int K, int ldc, int Ncols, int m0, int n0, __half* sm)
{
    const int ARR = 128 * SSTR;        // halves per array
    const int STG = 2 * ARR;           // stage: A, B

    const int tid = threadIdx.x, lane = tid & 31, wid = tid >> 5;
    const int wm = wid & 1, wn = wid >> 1;

    const uint32_t smb = (uint32_t)__cvta_generic_to_shared(sm);

    int srow[4], sg[4];
    #pragma unroll
    for (int i = 0; i < 4; i++) { int idx = i * 256 + tid; srow[i] = idx >> 3; sg[i] = idx & 7; }

    auto issue = [&](int c, int s) {
        const int kc = c * 64;
        #pragma unroll
        for (int i = 0; i < 4; i++) {
            int row = srow[i], g = sg[i];
            size_t ga = (size_t)(m0 + row) * K + kc + g * 8;
            size_t gb = (size_t)(n0 + row) * K + kc + g * 8;
            uint32_t so = smb + (uint32_t)(s * STG + row * SSTR + g * 8) * 2;
            CPA16(so + 0 * ARR * 2, A + ga);
            CPA16(so + 1 * ARR * 2, B + gb);
        }
    };

    float acc[4][4][4];
    #pragma unroll
    for (int i = 0; i < 4; i++)
        #pragma unroll
        for (int j = 0; j < 4; j++)
            #pragma unroll
            for (int q = 0; q < 4; q++) acc[i][j][q] = 0.f;

    const int a_lrow = lane & 15, a_lcol = (lane >> 4) * 8;
    const int b_lrow = (lane & 7) + ((lane >> 4) * 8), b_lcol = ((lane >> 3) & 1) * 8;

    const int KC = K >> 6;
    issue(0, 0); CPC();

    for (int c = 0; c < KC; c++) {
        CPW0();            // only pending group = chunk c
        __syncthreads();   // stage c&1 visible to all; orders reuse of stage (c+1)&1
        if (c + 1 < KC) { issue(c + 1, (c + 1) & 1); CPC(); }

        const int st = (c & 1) * STG;
        const uint32_t baseA = smb + (uint32_t)(st + 0 * ARR) * 2;
        const uint32_t baseB = smb + (uint32_t)(st + 1 * ARR) * 2;

        #pragma unroll
        for (int kk = 0; kk < 4; kk++) {
            const int kb = kk * 16;
            uint32_t bf[4][2];
            #pragma unroll
            for (int nn = 0; nn < 2; nn++) {
                uint32_t off = (uint32_t)((wn * 32 + nn * 16 + b_lrow) * SSTR + kb + b_lcol) * 2;
                LDSM_X4(bf[nn*2][0], bf[nn*2][1], bf[nn*2+1][0], bf[nn*2+1][1], baseB + off);
            }
            #pragma unroll
            for (int mi = 0; mi < 4; mi++) {
                uint32_t off = (uint32_t)((wm * 64 + mi * 16 + a_lrow) * SSTR + kb + a_lcol) * 2;
                uint32_t ah[4];
                LDSM_X4(ah[0], ah[1], ah[2], ah[3], baseA + off);
                #pragma unroll
                for (int ni = 0; ni < 4; ni++)
                    mma16816(acc[mi][ni], ah, bf[ni]);
            }
        }
    }

    const int qrow = lane >> 2, qk = (lane & 3) * 2;
    #pragma unroll
    for (int mi = 0; mi < 4; mi++) {
        #pragma unroll
        for (int ni = 0; ni < 4; ni++) {
            int c0 = n0 + wn * 32 + ni * 8 + qk;
            if (c0 >= Ncols) continue;
            int r0 = m0 + wm * 64 + mi * 16 + qrow;
            float b0 = bias[c0], b1v = bias[c0 + 1];
            #pragma unroll
            for (int h = 0; h < 2; h++) {
                int m = r0 + h * 8;
                float v0 = acc[mi][ni][h*2+0] + b0;
                float v1 = acc[mi][ni][h*2+1] + b1v;
                if (EPI == 1) {
                    float2 rr = *reinterpret_cast<const float2*>(res + (size_t)m * ldc + c0);
                    v0 += rr.x; v1 += rr.y;
                }
                if (EPI == 2) {
                    v0 = 0.5f * v0 * (1.0f + erff(v0 * 0.70710678118654752f));
                    v1 = 0.5f * v1 * (1.0f + erff(v1 * 0.70710678118654752f));
                }
                if (EPI == 2 || EPI == 3) {
                    *reinterpret_cast<__half2*>(Ch + (size_t)m * ldc + c0) =
                        __floats2half2_rn(v0, v1);
                } else {
                    *reinterpret_cast<float2*>(Cf + (size_t)m * ldc + c0) =
                        make_float2(v0, v1);
                }
            }
        }
    }
}

template<int EPI>
__global__ __launch_bounds__(256, 3) void mma_gemm(
    const __half* __restrict__ A, const __half* __restrict__ B,
    const float* __restrict__ bias, const float* __restrict__ res,
    float* __restrict__ Cf, __half* __restrict__ Ch,
    int K, int ldc, int Ncols)
{
    extern __shared__ __half sm[];
    gemm_body<EPI>(A, B, bias, res, Cf, Ch, K, ldc, Ncols,
                   blockIdx.y * 128, blockIdx.x * 128, sm);
}

// fused pair: value GEMM (768 CTAs) + offset/attention GEMM (256 CTAs)
__global__ __launch_bounds__(256, 3) void gemm_pair_kernel(
    const __half* __restrict__ xf, const __half* __restrict__ wvt,
    const float* __restrict__ bv, __half* __restrict__ val,
    const __half* __restrict__ xq, const __half* __restrict__ wct,
    const float* __restrict__ bcomb, float* __restrict__ offatt)
{
    extern __shared__ __half sm[];
    int t = blockIdx.x;
    if (t < 768) {
        gemm_body<3>(xf, wvt, bv, nullptr, nullptr, val,
                     CC, CC, CC, (t / 6) * 128, (t % 6) * 128, sm);
    } else {
        int t2 = t - 768;
        gemm_body<0>(xq, wct, bcomb, nullptr, offatt, nullptr,
                     CC, 192, 144, (t2 / 2) * 128, (t2 % 2) * 128, sm);
    }
}

// ---------------- sampling: softmax(4) + bilinear -> fp16 ----------------
__global__ __launch_bounds__(256) void sample_kernel(
    const __half* __restrict__ value,
    const float* __restrict__ refp,
    const float* __restrict__ offatt,
    __half* __restrict__ oh)
{
    int gid = blockIdx.x * 4 + (threadIdx.x >> 6);
    int di  = threadIdx.x & 63;
    int head = gid % NHH;
    int bq   = gid / NHH;
    int b    = bq / LQ;

    const float* rp = refp + (size_t)bq * 2;
    float rx = rp[0], ry = rp[1];
    const float* op = offatt + (size_t)bq * 192 + head * 8;
    const float* lp = offatt + (size_t)bq * 192 + 96 + head * 4;

    float l0 = lp[0], l1 = lp[1], l2 = lp[2], l3 = lp[3];
    float mx = fmaxf(fmaxf(l0, l1), fmaxf(l2, l3));
    float e0 = expf(l0 - mx), e1 = expf(l1 - mx), e2 = expf(l2 - mx), e3 = expf(l3 - mx);
    float inv = 1.0f / (e0 + e1 + e2 + e3);
    float wsm[4] = {e0 * inv, e1 * inv, e2 * inv, e3 * inv};

    const __half* vb = value + (size_t)b * (HH * WW) * CC + head * DH + di;
    float acc = 0.f;
    #pragma unroll
    for (int p = 0; p < 4; p++) {
        float x = rx * (float)WW + op[p*2+0] - 0.5f;
        float y = ry * (float)HH + op[p*2+1] - 0.5f;
        float x0f = floorf(x), y0f = floorf(y);
        int   x0 = (int)x0f,  y0 = (int)y0f;
        float wx1 = x - x0f, wy1 = y - y0f;
        float wx0 = 1.f - wx1, wy0 = 1.f - wy1;
        float s = 0.f;
        #pragma unroll
        for (int cc = 0; cc < 4; cc++) {
            int xi = x0 + (cc & 1);
            int yi = y0 + (cc >> 1);
            float w = ((cc & 1) ? wx1 : wx0) * ((cc >> 1) ? wy1 : wy0);
            if (xi >= 0 && xi < WW && yi >= 0 && yi < HH)
                s += w * __half2float(vb[(size_t)(yi * WW + xi) * CC]);
        }
        acc += wsm[p] * s;
    }
    oh[(size_t)bq * CC + head * DH + di] = __float2half(acc);
}

// ---------------- launch ----------------
extern "C" void kernel_launch(void* const* d_in, const int* in_sizes, int n_in,
                              void* d_out, int out_size)
{
    const float* query = (const float*)d_in[0];
    const float* refp  = (const float*)d_in[1];
    const float* feat  = (const float*)d_in[2];
    int p = n_in - 18;
    const float* qn_g  = (const float*)d_in[p + 0];
    const float* qn_b  = (const float*)d_in[p + 1];
    const float* fn_g  = (const float*)d_in[p + 2];
    const float* fn_b  = (const float*)d_in[p + 3];
    const float* Wv    = (const float*)d_in[p + 4];
    const float* bv    = (const float*)d_in[p + 5];
    const float* Woff  = (const float*)d_in[p + 6];
    const float* boff  = (const float*)d_in[p + 7];
    const float* Watt  = (const float*)d_in[p + 8];
    const float* batt  = (const float*)d_in[p + 9];
    const float* Wout  = (const float*)d_in[p + 10];
    const float* bout  = (const float*)d_in[p + 11];
    const float* ffn_g = (const float*)d_in[p + 12];
    const float* ffn_b = (const float*)d_in[p + 13];
    const float* W1    = (const float*)d_in[p + 14];
    const float* b1    = (const float*)d_in[p + 15];
    const float* W2    = (const float*)d_in[p + 16];
    const float* b2    = (const float*)d_in[p + 17];
    float* out = (float*)d_out;

    __half *xf, *xq, *val, *s, *hmid;
    __half *wvt, *wot, *wct, *w1t, *w2t;
    float *offatt, *bcomb, *b1p;
    cudaGetSymbolAddress((void**)&xf, g_xf);
    cudaGetSymbolAddress((void**)&xq, g_xq);
    cudaGetSymbolAddress((void**)&val, g_value);
    cudaGetSymbolAddress((void**)&s, g_s);
    cudaGetSymbolAddress((void**)&hmid, g_hmid);
    cudaGetSymbolAddress((void**)&wvt, g_wvt);
    cudaGetSymbolAddress((void**)&wot, g_wot);
    cudaGetSymbolAddress((void**)&wct, g_wct);
    cudaGetSymbolAddress((void**)&w1t, g_w1t);
    cudaGetSymbolAddress((void**)&w2t, g_w2t);
    cudaGetSymbolAddress((void**)&offatt, g_offatt);
    cudaGetSymbolAddress((void**)&bcomb, g_bcomb);
    cudaGetSymbolAddress((void**)&b1p, g_b1p);

    const int SMEM_GEMM = 2 * 2 * 128 * SSTR * 2;   // 73728 B (2-stage) -> 3 CTAs/SM
    cudaFuncSetAttribute(mma_gemm<1>, cudaFuncAttributeMaxDynamicSharedMemorySize, SMEM_GEMM);
    cudaFuncSetAttribute(mma_gemm<2>, cudaFuncAttributeMaxDynamicSharedMemorySize, SMEM_GEMM);
    cudaFuncSetAttribute(gemm_pair_kernel, cudaFuncAttributeMaxDynamicSharedMemorySize, SMEM_GEMM);

    // 1. fused prep: weight transpose + LN(feat) + LN(query)
    prep_kernel<<<6721 + 2 * MROWS, 256>>>(feat, query, fn_g, fn_b, qn_g, qn_b, xf, xq,
        Wv, Wout, Woff, Watt, W1, W2, wvt, wot, wct, w1t, w2t,
        boff, batt, b1, bcomb, b1p);

    // 2. fused GEMM pair: value + offsets/logits
    gemm_pair_kernel<<<1024, 256, SMEM_GEMM>>>(xf, wvt, bv, val, xq, wct, bcomb, offatt);

    // 3. softmax + bilinear sampling -> fp16
    sample_kernel<<<MROWS * NHH / 4, 256>>>(val, refp, offatt, s);

    // 4. out = query + samp @ Wout + bout
    mma_gemm<1><<<dim3(6, 128), 256, SMEM_GEMM>>>(s, wot, bout, query,
        out, nullptr, CC, CC, CC);

    // 5. FFN
    ln_kernel<<<MROWS, 256>>>(out, ffn_g, ffn_b, xf);
    mma_gemm<2><<<dim3(2, 128), 256, SMEM_GEMM>>>(xf, w1t, b1p, nullptr,
        nullptr, hmid, CC, HID, HID);
    mma_gemm<1><<<dim3(6, 128), 256, SMEM_GEMM>>>(hmid, w2t, b2, out,
        out, nullptr, HID, CC, CC);
}

// round 13
// speedup vs baseline: 2.1105x; 1.3909x over previous
#include <cuda_runtime.h>
#include <cuda_fp16.h>
#include <math.h>
#include <cstdint>

// Problem constants
#define B_    4
#define LQ    4096
#define CC    768
#define NHH   12
#define DH    64
#define HH    64
#define WW    64
#define HID   192
#define MROWS (B_*LQ)   // 16384

// ---------------- scratch ----------------
__device__ __align__(16) __half g_xf[MROWS*CC];                     // LN(feat) fp16
__device__ __align__(16) __half g_xq[MROWS*CC];                     // LN(query) fp16
__device__ __align__(16) __half g_value[MROWS*CC];                  // value fp16
__device__ __align__(16) float  g_offatt[MROWS*192];                // off(96)+logits(48)+pad
__device__ __align__(16) __half g_s[MROWS*CC];                      // sampled fp16
__device__ __align__(16) __half g_hmid[MROWS*HID];                  // FFN hidden fp16
// transposed weights [Npad][K] fp16
__device__ __align__(16) __half g_wvt[CC*CC];
__device__ __align__(16) __half g_wot[CC*CC];
__device__ __align__(16) __half g_wct[256*CC];
__device__ __align__(16) __half g_w1t[256*CC];
__device__ __align__(16) __half g_w2t[CC*HID];
__device__ float g_bcomb[256], g_b1p[256];

// ---------------- vectorized LN body ----------------
__device__ __forceinline__ void ln_row(const float* __restrict__ in,
                                       const float* __restrict__ gamma,
                                       const float* __restrict__ beta,
                                       __half* __restrict__ oh, int row)
{
    int t = threadIdx.x;
    float4 v = make_float4(0.f, 0.f, 0.f, 0.f);
    if (t < 192) v = *reinterpret_cast<const float4*>(in + (size_t)row * CC + t * 4);
    float s  = v.x + v.y + v.z + v.w;
    float s2 = v.x*v.x + v.y*v.y + v.z*v.z + v.w*v.w;
    #pragma unroll
    for (int o = 16; o; o >>= 1) {
        s  += __shfl_xor_sync(0xffffffffu, s,  o);
        s2 += __shfl_xor_sync(0xffffffffu, s2, o);
    }
    __shared__ float ssum[8], ssum2[8];
    int w = t >> 5;
    if ((t & 31) == 0) { ssum[w] = s; ssum2[w] = s2; }
    __syncthreads();
    float S = 0.f, S2 = 0.f;
    #pragma unroll
    for (int i = 0; i < 8; i++) { S += ssum[i]; S2 += ssum2[i]; }
    float mean = S * (1.0f / CC);
    float var  = S2 * (1.0f / CC) - mean * mean;
    float inv  = rsqrtf(var + 1e-5f);
    if (t < 192) {
        float4 gg = *reinterpret_cast<const float4*>(gamma + t * 4);
        float4 bb = *reinterpret_cast<const float4*>(beta  + t * 4);
        __half2 h0 = __floats2half2_rn((v.x - mean) * inv * gg.x + bb.x,
                                       (v.y - mean) * inv * gg.y + bb.y);
        __half2 h1 = __floats2half2_rn((v.z - mean) * inv * gg.z + bb.z,
                                       (v.w - mean) * inv * gg.w + bb.w);
        *reinterpret_cast<__half2*>(oh + (size_t)row * CC + t * 4)     = h0;
        *reinterpret_cast<__half2*>(oh + (size_t)row * CC + t * 4 + 2) = h1;
    }
}

// ---------------- fused prep: weight transpose + both LNs ----------------
__global__ __launch_bounds__(256) void prep_kernel(
    const float* __restrict__ feat, const float* __restrict__ query,
    const float* __restrict__ fn_g, const float* __restrict__ fn_b,
    const float* __restrict__ qn_g, const float* __restrict__ qn_b,
    __half* __restrict__ xf, __half* __restrict__ xq,
    const float* Wv, const float* Wout, const float* Woff, const float* Watt,
    const float* W1, const float* W2,
    __half* wvt, __half* wot, __half* wct, __half* w1t, __half* w2t,
    const float* boff, const float* batt, const float* b1,
    float* bcomb, float* b1p)
{
    int blk = blockIdx.x;
    if (blk >= 6721) {
        int row = blk - 6721;
        if (row < MROWS) ln_row(feat, fn_g, fn_b, xf, row);
        else             ln_row(query, qn_g, qn_b, xq, row - MROWS);
        return;
    }
    const float* src; __half* dst; int K, N, Npad, rel;
    if (blk < 2304)      { src=Wv;   dst=wvt;        K=CC;  N=CC;  Npad=CC;  rel=blk; }
    else if (blk < 4608) { src=Wout; dst=wot;        K=CC;  N=CC;  Npad=CC;  rel=blk-2304; }
    else if (blk < 4896) { src=Woff; dst=wct;        K=CC;  N=96;  Npad=96;  rel=blk-4608; }
    else if (blk < 5376) { src=Watt; dst=wct+96*CC;  K=CC;  N=48;  Npad=160; rel=blk-4896; }
    else if (blk < 6144) { src=W1;   dst=w1t;        K=CC;  N=HID; Npad=256; rel=blk-5376; }
    else if (blk < 6720) { src=W2;   dst=w2t;        K=HID; N=CC;  Npad=CC;  rel=blk-6144; }
    else {
        int i = threadIdx.x;
        bcomb[i] = (i < 96) ? boff[i] : (i < 144 ? batt[i - 96] : 0.0f);
        b1p[i]   = (i < 192) ? b1[i] : 0.0f;
        return;
    }
    int idx = rel * 256 + threadIdx.x;
    if (idx >= Npad * K) return;
    int n = idx / K, k = idx - n * K;
    float v = (n < N) ? src[(size_t)k * N + n] : 0.0f;
    dst[idx] = __float2half(v);
}

__global__ __launch_bounds__(256) void ln_kernel(const float* __restrict__ in,
                                                 const float* __restrict__ gamma,
                                                 const float* __restrict__ beta,
                                                 __half* __restrict__ oh)
{
    ln_row(in, gamma, beta, oh, blockIdx.x);
}

// ---------------- GEMM core: BK=64, 3-stage, 2 CTAs/SM, reg double-buffer ----
#define SSTR 72  // smem row stride in halfs (64 + 8 pad)

__device__ __forceinline__ void mma16816(float* d, const uint32_t* a, const uint32_t* b) {
    asm volatile(
        "mma.sync.aligned.m16n8k16.row.col.f32.f16.f16.f32 "
        "{%0,%1,%2,%3}, {%4,%5,%6,%7}, {%8,%9}, {%0,%1,%2,%3};"
        : "+f"(d[0]), "+f"(d[1]), "+f"(d[2]), "+f"(d[3])
        : "r"(a[0]), "r"(a[1]), "r"(a[2]), "r"(a[3]), "r"(b[0]), "r"(b[1]));
}
#define LDSM_X4(R0,R1,R2,R3,ADDR) \
    asm volatile("ldmatrix.sync.aligned.m8n8.x4.shared.b16 {%0,%1,%2,%3}, [%4];" \
        : "=r"(R0), "=r"(R1), "=r"(R2), "=r"(R3) : "r"(ADDR))
#define CPA16(DST,SRC) \
    asm volatile("cp.async.cg.shared.global [%0], [%1], 16;" :: "r"(DST), "l"(SRC) : "memory")
#define CPC() asm volatile("cp.async.commit_group;" ::: "memory")
#define CPW1() asm volatile("cp.async.wait_group 1;" ::: "memory")
#define CPW0() asm volatile("cp.async.wait_group 0;" ::: "memory")

// EPI: 0 bias->fp32; 1 bias+res->fp32; 2 bias+GELU->fp16; 3 bias->fp16
template<int EPI>
__device__ __forceinline__ void gemm_body(
    const __half* __restrict__ A, const __half* __restrict__ B,
    const float* __restrict__ bias, const float* __restrict__ res,
    float* __restrict__ Cf, __half* __restrict__ Ch,
    int K, int ldc, int Ncols, int m0, int n0, __half* sm)
{
    const int ARR = 128 * SSTR;
    const int STG = 2 * ARR;

    const int tid = threadIdx.x, lane = tid & 31, wid = tid >> 5;
    const int wm = wid & 1, wn = wid >> 1;

    const uint32_t smb = (uint32_t)__cvta_generic_to_shared(sm);

    int srow[4], sg[4];
    #pragma unroll
    for (int i = 0; i < 4; i++) { int idx = i * 256 + tid; srow[i] = idx >> 3; sg[i] = idx & 7; }

    auto issue = [&](int c, int s) {
        const int kc = c * 64;
        #pragma unroll
        for (int i = 0; i < 4; i++) {
            int row = srow[i], g = sg[i];
            size_t ga = (size_t)(m0 + row) * K + kc + g * 8;
            size_t gb = (size_t)(n0 + row) * K + kc + g * 8;
            uint32_t so = smb + (uint32_t)(s * STG + row * SSTR + g * 8) * 2;
            CPA16(so + 0 * ARR * 2, A + ga);
            CPA16(so + 1 * ARR * 2, B + gb);
        }
    };

    float acc[4][4][4];
    #pragma unroll
    for (int i = 0; i < 4; i++)
        #pragma unroll
        for (int j = 0; j < 4; j++)
            #pragma unroll
            for (int q = 0; q < 4; q++) acc[i][j][q] = 0.f;

    const int a_lrow = lane & 15, a_lcol = (lane >> 4) * 8;
    const int b_lrow = (lane & 7) + ((lane >> 4) * 8), b_lcol = ((lane >> 3) & 1) * 8;

    // fragment double buffers
    uint32_t bf[2][4][2], af[2][4][4];

    auto load_frags = [&](uint32_t baseA, uint32_t baseB, int kk, int buf) {
        const int kb = kk * 16;
        #pragma unroll
        for (int nn = 0; nn < 2; nn++) {
            uint32_t off = (uint32_t)((wn * 32 + nn * 16 + b_lrow) * SSTR + kb + b_lcol) * 2;
            LDSM_X4(bf[buf][nn*2][0], bf[buf][nn*2][1], bf[buf][nn*2+1][0], bf[buf][nn*2+1][1], baseB + off);
        }
        #pragma unroll
        for (int mi = 0; mi < 4; mi++) {
            uint32_t off = (uint32_t)((wm * 64 + mi * 16 + a_lrow) * SSTR + kb + a_lcol) * 2;
            LDSM_X4(af[buf][mi][0], af[buf][mi][1], af[buf][mi][2], af[buf][mi][3], baseA + off);
        }
    };

    const int KC = K >> 6;
    issue(0, 0); CPC();
    issue(1, 1); CPC();

    for (int c = 0; c < KC; c++) {
        if (c == KC - 1) { CPW0(); } else { CPW1(); }
        __syncthreads();
        if (c + 2 < KC) { issue(c + 2, (c + 2) % 3); CPC(); }

        const int st = (c % 3) * STG;
        const uint32_t baseA = smb + (uint32_t)(st + 0 * ARR) * 2;
        const uint32_t baseB = smb + (uint32_t)(st + 1 * ARR) * 2;

        load_frags(baseA, baseB, 0, 0);
        #pragma unroll
        for (int kk = 0; kk < 4; kk++) {
            int cur = kk & 1;
            if (kk < 3) load_frags(baseA, baseB, kk + 1, cur ^ 1);
            #pragma unroll
            for (int mi = 0; mi < 4; mi++)
                #pragma unroll
                for (int ni = 0; ni < 4; ni++)
                    mma16816(acc[mi][ni], af[cur][mi], bf[cur][ni]);
        }
    }

    const int qrow = lane >> 2, qk = (lane & 3) * 2;
    #pragma unroll
    for (int mi = 0; mi < 4; mi++) {
        #pragma unroll
        for (int ni = 0; ni < 4; ni++) {
            int c0 = n0 + wn * 32 + ni * 8 + qk;
            if (c0 >= Ncols) continue;
            int r0 = m0 + wm * 64 + mi * 16 + qrow;
            float b0 = bias[c0], b1v = bias[c0 + 1];
            #pragma unroll
            for (int h = 0; h < 2; h++) {
                int m = r0 + h * 8;
                float v0 = acc[mi][ni][h*2+0] + b0;
                float v1 = acc[mi][ni][h*2+1] + b1v;
                if (EPI == 1) {
                    float2 rr = *reinterpret_cast<const float2*>(res + (size_t)m * ldc + c0);
                    v0 += rr.x; v1 += rr.y;
                }
                if (EPI == 2) {
                    v0 = 0.5f * v0 * (1.0f + erff(v0 * 0.70710678118654752f));
                    v1 = 0.5f * v1 * (1.0f + erff(v1 * 0.70710678118654752f));
                }
                if (EPI == 2 || EPI == 3) {
                    *reinterpret_cast<__half2*>(Ch + (size_t)m * ldc + c0) =
                        __floats2half2_rn(v0, v1);
                } else {
                    *reinterpret_cast<float2*>(Cf + (size_t)m * ldc + c0) =
                        make_float2(v0, v1);
                }
            }
        }
    }
}

template<int EPI>
__global__ __launch_bounds__(256, 2) void mma_gemm(
    const __half* __restrict__ A, const __half* __restrict__ B,
    const float* __restrict__ bias, const float* __restrict__ res,
    float* __restrict__ Cf, __half* __restrict__ Ch,
    int K, int ldc, int Ncols)
{
    extern __shared__ __half sm[];
    gemm_body<EPI>(A, B, bias, res, Cf, Ch, K, ldc, Ncols,
                   blockIdx.y * 128, blockIdx.x * 128, sm);
}

// fused pair: value GEMM (768 CTAs) + offset/attention GEMM (256 CTAs)
__global__ __launch_bounds__(256, 2) void gemm_pair_kernel(
    const __half* __restrict__ xf, const __half* __restrict__ wvt,
    const float* __restrict__ bv, __half* __restrict__ val,
    const __half* __restrict__ xq, const __half* __restrict__ wct,
    const float* __restrict__ bcomb, float* __restrict__ offatt)
{
    extern __shared__ __half sm[];
    int t = blockIdx.x;
    if (t < 768) {
        gemm_body<3>(xf, wvt, bv, nullptr, nullptr, val,
                     CC, CC, CC, (t / 6) * 128, (t % 6) * 128, sm);
    } else {
        int t2 = t - 768;
        gemm_body<0>(xq, wct, bcomb, nullptr, offatt, nullptr,
                     CC, 192, 144, (t2 / 2) * 128, (t2 % 2) * 128, sm);
    }
}

// ---------------- sampling: softmax(4) + bilinear -> fp16 ----------------
__global__ __launch_bounds__(256) void sample_kernel(
    const __half* __restrict__ value,
    const float* __restrict__ refp,
    const float* __restrict__ offatt,
    __half* __restrict__ oh)
{
    int gid = blockIdx.x * 4 + (threadIdx.x >> 6);
    int di  = threadIdx.x & 63;
    int head = gid % NHH;
    int bq   = gid / NHH;
    int b    = bq / LQ;

    const float* rp = refp + (size_t)bq * 2;
    float rx = rp[0], ry = rp[1];
    const float* op = offatt + (size_t)bq * 192 + head * 8;
    const float* lp = offatt + (size_t)bq * 192 + 96 + head * 4;

    float l0 = lp[0], l1 = lp[1], l2 = lp[2], l3 = lp[3];
    float mx = fmaxf(fmaxf(l0, l1), fmaxf(l2, l3));
    float e0 = expf(l0 - mx), e1 = expf(l1 - mx), e2 = expf(l2 - mx), e3 = expf(l3 - mx);
    float inv = 1.0f / (e0 + e1 + e2 + e3);
    float wsm[4] = {e0 * inv, e1 * inv, e2 * inv, e3 * inv};

    const __half* vb = value + (size_t)b * (HH * WW) * CC + head * DH + di;
    float acc = 0.f;
    #pragma unroll
    for (int p = 0; p < 4; p++) {
        float x = rx * (float)WW + op[p*2+0] - 0.5f;
        float y = ry * (float)HH + op[p*2+1] - 0.5f;
        float x0f = floorf(x), y0f = floorf(y);
        int   x0 = (int)x0f,  y0 = (int)y0f;
        float wx1 = x - x0f, wy1 = y - y0f;
        float wx0 = 1.f - wx1, wy0 = 1.f - wy1;
        float s = 0.f;
        #pragma unroll
        for (int cc = 0; cc < 4; cc++) {
            int xi = x0 + (cc & 1);
            int yi = y0 + (cc >> 1);
            float w = ((cc & 1) ? wx1 : wx0) * ((cc >> 1) ? wy1 : wy0);
            if (xi >= 0 && xi < WW && yi >= 0 && yi < HH)
                s += w * __half2float(vb[(size_t)(yi * WW + xi) * CC]);
        }
        acc += wsm[p] * s;
    }
    oh[(size_t)bq * CC + head * DH + di] = __float2half(acc);
}

// ---------------- launch ----------------
extern "C" void kernel_launch(void* const* d_in, const int* in_sizes, int n_in,
                              void* d_out, int out_size)
{
    const float* query = (const float*)d_in[0];
    const float* refp  = (const float*)d_in[1];
    const float* feat  = (const float*)d_in[2];
    int p = n_in - 18;
    const float* qn_g  = (const float*)d_in[p + 0];
    const float* qn_b  = (const float*)d_in[p + 1];
    const float* fn_g  = (const float*)d_in[p + 2];
    const float* fn_b  = (const float*)d_in[p + 3];
    const float* Wv    = (const float*)d_in[p + 4];
    const float* bv    = (const float*)d_in[p + 5];
    const float* Woff  = (const float*)d_in[p + 6];
    const float* boff  = (const float*)d_in[p + 7];
    const float* Watt  = (const float*)d_in[p + 8];
    const float* batt  = (const float*)d_in[p + 9];
    const float* Wout  = (const float*)d_in[p + 10];
    const float* bout  = (const float*)d_in[p + 11];
    const float* ffn_g = (const float*)d_in[p + 12];
    const float* ffn_b = (const float*)d_in[p + 13];
    const float* W1    = (const float*)d_in[p + 14];
    const float* b1    = (const float*)d_in[p + 15];
    const float* W2    = (const float*)d_in[p + 16];
    const float* b2    = (const float*)d_in[p + 17];
    float* out = (float*)d_out;

    __half *xf, *xq, *val, *s, *hmid;
    __half *wvt, *wot, *wct, *w1t, *w2t;
    float *offatt, *bcomb, *b1p;
    cudaGetSymbolAddress((void**)&xf, g_xf);
    cudaGetSymbolAddress((void**)&xq, g_xq);
    cudaGetSymbolAddress((void**)&val, g_value);
    cudaGetSymbolAddress((void**)&s, g_s);
    cudaGetSymbolAddress((void**)&hmid, g_hmid);
    cudaGetSymbolAddress((void**)&wvt, g_wvt);
    cudaGetSymbolAddress((void**)&wot, g_wot);
    cudaGetSymbolAddress((void**)&wct, g_wct);
    cudaGetSymbolAddress((void**)&w1t, g_w1t);
    cudaGetSymbolAddress((void**)&w2t, g_w2t);
    cudaGetSymbolAddress((void**)&offatt, g_offatt);
    cudaGetSymbolAddress((void**)&bcomb, g_bcomb);
    cudaGetSymbolAddress((void**)&b1p, g_b1p);

    const int SMEM_GEMM = 3 * 2 * 128 * SSTR * 2;   // 110592 B (3-stage) -> 2 CTAs/SM
    cudaFuncSetAttribute(mma_gemm<1>, cudaFuncAttributeMaxDynamicSharedMemorySize, SMEM_GEMM);
    cudaFuncSetAttribute(mma_gemm<2>, cudaFuncAttributeMaxDynamicSharedMemorySize, SMEM_GEMM);
    cudaFuncSetAttribute(gemm_pair_kernel, cudaFuncAttributeMaxDynamicSharedMemorySize, SMEM_GEMM);

    // 1. fused prep: weight transpose + LN(feat) + LN(query)
    prep_kernel<<<6721 + 2 * MROWS, 256>>>(feat, query, fn_g, fn_b, qn_g, qn_b, xf, xq,
        Wv, Wout, Woff, Watt, W1, W2, wvt, wot, wct, w1t, w2t,
        boff, batt, b1, bcomb, b1p);

    // 2. fused GEMM pair: value + offsets/logits
    gemm_pair_kernel<<<1024, 256, SMEM_GEMM>>>(xf, wvt, bv, val, xq, wct, bcomb, offatt);

    // 3. softmax + bilinear sampling -> fp16
    sample_kernel<<<MROWS * NHH / 4, 256>>>(val, refp, offatt, s);

    // 4. out = query + samp @ Wout + bout
    mma_gemm<1><<<dim3(6, 128), 256, SMEM_GEMM>>>(s, wot, bout, query,
        out, nullptr, CC, CC, CC);

    // 5. FFN
    ln_kernel<<<MROWS, 256>>>(out, ffn_g, ffn_b, xf);
    mma_gemm<2><<<dim3(2, 128), 256, SMEM_GEMM>>>(xf, w1t, b1p, nullptr,
        nullptr, hmid, CC, HID, HID);
    mma_gemm<1><<<dim3(6, 128), 256, SMEM_GEMM>>>(hmid, w2t, b2, out,
        out, nullptr, HID, CC, CC);
}

// round 14
// speedup vs baseline: 2.1416x; 1.0147x over previous
#include <cuda_runtime.h>
#include <cuda_fp16.h>
#include <math.h>
#include <cstdint>

// Problem constants
#define B_    4
#define LQ    4096
#define CC    768
#define NHH   12
#define DH    64
#define HH    64
#define WW    64
#define HID   192
#define MROWS (B_*LQ)   // 16384

// ---------------- scratch ----------------
__device__ __align__(16) __half g_xf[MROWS*CC];                     // LN out fp16 (reused)
__device__ __align__(16) __half g_xq[MROWS*CC];                     // LN(query) fp16
__device__ __align__(16) __half g_value[MROWS*CC];                  // value fp16
__device__ __align__(16) float  g_offatt[MROWS*192];                // off(96)+logits(48)+pad
__device__ __align__(16) __half g_s[MROWS*CC];                      // sampled fp16
__device__ __align__(16) __half g_hmid[MROWS*HID];                  // FFN hidden fp16
__device__ __align__(16) __half g_out16[MROWS*CC];                  // step4 result fp16
// transposed weights [Npad][K] fp16
__device__ __align__(16) __half g_wvt[CC*CC];
__device__ __align__(16) __half g_wot[CC*CC];
__device__ __align__(16) __half g_wct[256*CC];
__device__ __align__(16) __half g_w1t[256*CC];
__device__ __align__(16) __half g_w2t[CC*HID];
__device__ float g_bcomb[256], g_b1p[256];

// ---------------- LN bodies ----------------
__device__ __forceinline__ void ln_reduce_and_store(float4 v, const float* gamma,
                                                    const float* beta, __half* oh, int row)
{
    int t = threadIdx.x;
    float s  = v.x + v.y + v.z + v.w;
    float s2 = v.x*v.x + v.y*v.y + v.z*v.z + v.w*v.w;
    #pragma unroll
    for (int o = 16; o; o >>= 1) {
        s  += __shfl_xor_sync(0xffffffffu, s,  o);
        s2 += __shfl_xor_sync(0xffffffffu, s2, o);
    }
    __shared__ float ssum[8], ssum2[8];
    int w = t >> 5;
    if ((t & 31) == 0) { ssum[w] = s; ssum2[w] = s2; }
    __syncthreads();
    float S = 0.f, S2 = 0.f;
    #pragma unroll
    for (int i = 0; i < 8; i++) { S += ssum[i]; S2 += ssum2[i]; }
    float mean = S * (1.0f / CC);
    float var  = S2 * (1.0f / CC) - mean * mean;
    float inv  = rsqrtf(var + 1e-5f);
    if (t < 192) {
        float4 gg = *reinterpret_cast<const float4*>(gamma + t * 4);
        float4 bb = *reinterpret_cast<const float4*>(beta  + t * 4);
        __half2 h0 = __floats2half2_rn((v.x - mean) * inv * gg.x + bb.x,
                                       (v.y - mean) * inv * gg.y + bb.y);
        __half2 h1 = __floats2half2_rn((v.z - mean) * inv * gg.z + bb.z,
                                       (v.w - mean) * inv * gg.w + bb.w);
        *reinterpret_cast<__half2*>(oh + (size_t)row * CC + t * 4)     = h0;
        *reinterpret_cast<__half2*>(oh + (size_t)row * CC + t * 4 + 2) = h1;
    }
}

__device__ __forceinline__ void ln_row_f(const float* __restrict__ in,
                                         const float* gamma, const float* beta,
                                         __half* oh, int row)
{
    int t = threadIdx.x;
    float4 v = make_float4(0.f, 0.f, 0.f, 0.f);
    if (t < 192) v = *reinterpret_cast<const float4*>(in + (size_t)row * CC + t * 4);
    ln_reduce_and_store(v, gamma, beta, oh, row);
}

__device__ __forceinline__ void ln_row_h(const __half* __restrict__ in,
                                         const float* gamma, const float* beta,
                                         __half* oh, int row)
{
    int t = threadIdx.x;
    float4 v = make_float4(0.f, 0.f, 0.f, 0.f);
    if (t < 192) {
        __half2 a = *reinterpret_cast<const __half2*>(in + (size_t)row * CC + t * 4);
        __half2 b = *reinterpret_cast<const __half2*>(in + (size_t)row * CC + t * 4 + 2);
        float2 fa = __half22float2(a), fb = __half22float2(b);
        v = make_float4(fa.x, fa.y, fb.x, fb.y);
    }
    ln_reduce_and_store(v, gamma, beta, oh, row);
}

// ---------------- fused prep: coalesced weight transpose tiles + both LNs ------
// tile blocks [0,408): 64x64 smem-transpose tiles; block 408: bias; [409,..): LN rows
__global__ __launch_bounds__(256) void prep_kernel(
    const float* __restrict__ feat, const float* __restrict__ query,
    const float* __restrict__ fn_g, const float* __restrict__ fn_b,
    const float* __restrict__ qn_g, const float* __restrict__ qn_b,
    __half* __restrict__ xf, __half* __restrict__ xq,
    const float* __restrict__ Wv, const float* __restrict__ Wout,
    const float* __restrict__ Woff, const float* __restrict__ Watt,
    const float* __restrict__ W1, const float* __restrict__ W2,
    __half* wvt, __half* wot, __half* wct, __half* w1t, __half* w2t,
    const float* boff, const float* batt, const float* b1,
    float* bcomb, float* b1p)
{
    int blk = blockIdx.x;
    if (blk >= 409) {
        int row = blk - 409;
        if (row < MROWS) ln_row_f(feat, fn_g, fn_b, xf, row);
        else             ln_row_f(query, qn_g, qn_b, xq, row - MROWS);
        return;
    }
    if (blk == 408) {
        int i = threadIdx.x;
        bcomb[i] = (i < 96) ? boff[i] : (i < 144 ? batt[i - 96] : 0.0f);
        b1p[i]   = (i < 192) ? b1[i] : 0.0f;
        return;
    }
    // segments: s0 Wv [0,144), s1 Wout [144,288), s2 wct [288,324),
    //           s3 w1t [324,372), s4 w2t [372,408)
    int seg, rel, ntx, K, Npad;
    __half* dst;
    if (blk < 144)      { seg=0; rel=blk;     ntx=12; K=CC;  Npad=CC;  dst=g_wvt; }
    else if (blk < 288) { seg=1; rel=blk-144; ntx=12; K=CC;  Npad=CC;  dst=g_wot; }
    else if (blk < 324) { seg=2; rel=blk-288; ntx=3;  K=CC;  Npad=160; dst=g_wct; }
    else if (blk < 372) { seg=3; rel=blk-324; ntx=4;  K=CC;  Npad=256; dst=g_w1t; }
    else                { seg=4; rel=blk-372; ntx=12; K=HID; Npad=CC;  dst=g_w2t; }
    int ty = rel / ntx, tx = rel % ntx;
    int k0 = ty * 64, n0 = tx * 64;

    __shared__ __half tile[64][66];
    int tid = threadIdx.x;
    // load phase: consecutive threads -> consecutive n (coalesced source reads)
    #pragma unroll
    for (int it = 0; it < 16; it++) {
        int idx = it * 256 + tid;
        int kk = idx >> 6, nn = idx & 63;
        int k = k0 + kk, n = n0 + nn;
        float v = 0.0f;
        if (seg == 0)      { v = Wv  [(size_t)k * CC  + n]; }
        else if (seg == 1) { v = Wout[(size_t)k * CC  + n]; }
        else if (seg == 2) {
            if (n < 96)       v = Woff[(size_t)k * 96  + n];
            else if (n < 144) v = Watt[(size_t)k * 48  + (n - 96)];
        }
        else if (seg == 3) { if (n < HID) v = W1[(size_t)k * HID + n]; }
        else               { v = W2  [(size_t)k * CC  + n]; }
        tile[kk][nn] = __float2half(v);
    }
    __syncthreads();
    // write phase: consecutive threads -> consecutive k (coalesced dst writes)
    #pragma unroll
    for (int it = 0; it < 16; it++) {
        int idx = it * 256 + tid;
        int nn = idx >> 6, kk = idx & 63;
        int n = n0 + nn;
        if (n < Npad)
            dst[(size_t)n * K + k0 + kk] = tile[kk][nn];
    }
}

__global__ __launch_bounds__(256) void ln_h_kernel(const __half* __restrict__ in,
                                                   const float* __restrict__ gamma,
                                                   const float* __restrict__ beta,
                                                   __half* __restrict__ oh)
{
    ln_row_h(in, gamma, beta, oh, blockIdx.x);
}

// ---------------- GEMM core: BK=64, 3-stage, 2 CTAs/SM, reg double-buffer ----
#define SSTR 72  // smem row stride in halfs (64 + 8 pad)

__device__ __forceinline__ void mma16816(float* d, const uint32_t* a, const uint32_t* b) {
    asm volatile(
        "mma.sync.aligned.m16n8k16.row.col.f32.f16.f16.f32 "
        "{%0,%1,%2,%3}, {%4,%5,%6,%7}, {%8,%9}, {%0,%1,%2,%3};"
        : "+f"(d[0]), "+f"(d[1]), "+f"(d[2]), "+f"(d[3])
        : "r"(a[0]), "r"(a[1]), "r"(a[2]), "r"(a[3]), "r"(b[0]), "r"(b[1]));
}
#define LDSM_X4(R0,R1,R2,R3,ADDR) \
    asm volatile("ldmatrix.sync.aligned.m8n8.x4.shared.b16 {%0,%1,%2,%3}, [%4];" \
        : "=r"(R0), "=r"(R1), "=r"(R2), "=r"(R3) : "r"(ADDR))
#define CPA16(DST,SRC) \
    asm volatile("cp.async.cg.shared.global [%0], [%1], 16;" :: "r"(DST), "l"(SRC) : "memory")
#define CPC() asm volatile("cp.async.commit_group;" ::: "memory")
#define CPW1() asm volatile("cp.async.wait_group 1;" ::: "memory")
#define CPW0() asm volatile("cp.async.wait_group 0;" ::: "memory")

// EPI: 0 bias->fp32; 2 bias+GELU->fp16; 3 bias->fp16;
//      4 bias+res(f32)->fp16; 5 bias+res(f16)->fp32
template<int EPI>
__device__ __forceinline__ void gemm_body(
    const __half* __restrict__ A, const __half* __restrict__ B,
    const float* __restrict__ bias, const float* __restrict__ res,
    const __half* __restrict__ resh,
    float* __restrict__ Cf, __half* __restrict__ Ch,
    int K, int ldc, int Ncols, int m0, int n0, __half* sm)
{
    const int ARR = 128 * SSTR;
    const int STG = 2 * ARR;

    const int tid = threadIdx.x, lane = tid & 31, wid = tid >> 5;
    const int wm = wid & 1, wn = wid >> 1;

    const uint32_t smb = (uint32_t)__cvta_generic_to_shared(sm);

    int srow[4], sg[4];
    #pragma unroll
    for (int i = 0; i < 4; i++) { int idx = i * 256 + tid; srow[i] = idx >> 3; sg[i] = idx & 7; }

    auto issue = [&](int c, int s) {
        const int kc = c * 64;
        #pragma unroll
        for (int i = 0; i < 4; i++) {
            int row = srow[i], g = sg[i];
            size_t ga = (size_t)(m0 + row) * K + kc + g * 8;
            size_t gb = (size_t)(n0 + row) * K + kc + g * 8;
            uint32_t so = smb + (uint32_t)(s * STG + row * SSTR + g * 8) * 2;
            CPA16(so + 0 * ARR * 2, A + ga);
            CPA16(so + 1 * ARR * 2, B + gb);
        }
    };

    float acc[4][4][4];
    #pragma unroll
    for (int i = 0; i < 4; i++)
        #pragma unroll
        for (int j = 0; j < 4; j++)
            #pragma unroll
            for (int q = 0; q < 4; q++) acc[i][j][q] = 0.f;

    const int a_lrow = lane & 15, a_lcol = (lane >> 4) * 8;
    const int b_lrow = (lane & 7) + ((lane >> 4) * 8), b_lcol = ((lane >> 3) & 1) * 8;

    uint32_t bf[2][4][2], af[2][4][4];

    auto load_frags = [&](uint32_t baseA, uint32_t baseB, int kk, int buf) {
        const int kb = kk * 16;
        #pragma unroll
        for (int nn = 0; nn < 2; nn++) {
            uint32_t off = (uint32_t)((wn * 32 + nn * 16 + b_lrow) * SSTR + kb + b_lcol) * 2;
            LDSM_X4(bf[buf][nn*2][0], bf[buf][nn*2][1], bf[buf][nn*2+1][0], bf[buf][nn*2+1][1], baseB + off);
        }
        #pragma unroll
        for (int mi = 0; mi < 4; mi++) {
            uint32_t off = (uint32_t)((wm * 64 + mi * 16 + a_lrow) * SSTR + kb + a_lcol) * 2;
            LDSM_X4(af[buf][mi][0], af[buf][mi][1], af[buf][mi][2], af[buf][mi][3], baseA + off);
        }
    };

    const int KC = K >> 6;
    issue(0, 0); CPC();
    issue(1, 1); CPC();

    for (int c = 0; c < KC; c++) {
        if (c == KC - 1) { CPW0(); } else { CPW1(); }
        __syncthreads();
        if (c + 2 < KC) { issue(c + 2, (c + 2) % 3); CPC(); }

        const int st = (c % 3) * STG;
        const uint32_t baseA = smb + (uint32_t)(st + 0 * ARR) * 2;
        const uint32_t baseB = smb + (uint32_t)(st + 1 * ARR) * 2;

        load_frags(baseA, baseB, 0, 0);
        #pragma unroll
        for (int kk = 0; kk < 4; kk++) {
            int cur = kk & 1;
            if (kk < 3) load_frags(baseA, baseB, kk + 1, cur ^ 1);
            #pragma unroll
            for (int mi = 0; mi < 4; mi++)
                #pragma unroll
                for (int ni = 0; ni < 4; ni++)
                    mma16816(acc[mi][ni], af[cur][mi], bf[cur][ni]);
        }
    }

    const int qrow = lane >> 2, qk = (lane & 3) * 2;
    #pragma unroll
    for (int mi = 0; mi < 4; mi++) {
        #pragma unroll
        for (int ni = 0; ni < 4; ni++) {
            int c0 = n0 + wn * 32 + ni * 8 + qk;
            if (c0 >= Ncols) continue;
            int r0 = m0 + wm * 64 + mi * 16 + qrow;
            float b0 = bias[c0], b1v = bias[c0 + 1];
            #pragma unroll
            for (int h = 0; h < 2; h++) {
                int m = r0 + h * 8;
                float v0 = acc[mi][ni][h*2+0] + b0;
                float v1 = acc[mi][ni][h*2+1] + b1v;
                if (EPI == 4) {
                    float2 rr = *reinterpret_cast<const float2*>(res + (size_t)m * ldc + c0);
                    v0 += rr.x; v1 += rr.y;
                }
                if (EPI == 5) {
                    __half2 rr = *reinterpret_cast<const __half2*>(resh + (size_t)m * ldc + c0);
                    float2 fr = __half22float2(rr);
                    v0 += fr.x; v1 += fr.y;
                }
                if (EPI == 2) {
                    v0 = 0.5f * v0 * (1.0f + erff(v0 * 0.70710678118654752f));
                    v1 = 0.5f * v1 * (1.0f + erff(v1 * 0.70710678118654752f));
                }
                if (EPI == 2 || EPI == 3 || EPI == 4) {
                    *reinterpret_cast<__half2*>(Ch + (size_t)m * ldc + c0) =
                        __floats2half2_rn(v0, v1);
                } else {
                    *reinterpret_cast<float2*>(Cf + (size_t)m * ldc + c0) =
                        make_float2(v0, v1);
                }
            }
        }
    }
}

template<int EPI>
__global__ __launch_bounds__(256, 2) void mma_gemm(
    const __half* __restrict__ A, const __half* __restrict__ B,
    const float* __restrict__ bias, const float* __restrict__ res,
    const __half* __restrict__ resh,
    float* __restrict__ Cf, __half* __restrict__ Ch,
    int K, int ldc, int Ncols)
{
    extern __shared__ __half sm[];
    gemm_body<EPI>(A, B, bias, res, resh, Cf, Ch, K, ldc, Ncols,
                   blockIdx.y * 128, blockIdx.x * 128, sm);
}

// fused pair: value GEMM (768 CTAs) + offset/attention GEMM (256 CTAs)
__global__ __launch_bounds__(256, 2) void gemm_pair_kernel(
    const __half* __restrict__ xf, const __half* __restrict__ wvt,
    const float* __restrict__ bv, __half* __restrict__ val,
    const __half* __restrict__ xq, const __half* __restrict__ wct,
    const float* __restrict__ bcomb, float* __restrict__ offatt)
{
    extern __shared__ __half sm[];
    int t = blockIdx.x;
    if (t < 768) {
        gemm_body<3>(xf, wvt, bv, nullptr, nullptr, nullptr, val,
                     CC, CC, CC, (t / 6) * 128, (t % 6) * 128, sm);
    } else {
        int t2 = t - 768;
        gemm_body<0>(xq, wct, bcomb, nullptr, nullptr, offatt, nullptr,
                     CC, 192, 144, (t2 / 2) * 128, (t2 % 2) * 128, sm);
    }
}

// ---------------- sampling: softmax(4) + bilinear -> fp16 ----------------
__global__ __launch_bounds__(256) void sample_kernel(
    const __half* __restrict__ value,
    const float* __restrict__ refp,
    const float* __restrict__ offatt,
    __half* __restrict__ oh)
{
    int gid = blockIdx.x * 4 + (threadIdx.x >> 6);
    int di  = threadIdx.x & 63;
    int head = gid % NHH;
    int bq   = gid / NHH;
    int b    = bq / LQ;

    const float* rp = refp + (size_t)bq * 2;
    float rx = rp[0], ry = rp[1];
    const float* op = offatt + (size_t)bq * 192 + head * 8;
    const float* lp = offatt + (size_t)bq * 192 + 96 + head * 4;

    float l0 = lp[0], l1 = lp[1], l2 = lp[2], l3 = lp[3];
    float mx = fmaxf(fmaxf(l0, l1), fmaxf(l2, l3));
    float e0 = expf(l0 - mx), e1 = expf(l1 - mx), e2 = expf(l2 - mx), e3 = expf(l3 - mx);
    float inv = 1.0f / (e0 + e1 + e2 + e3);
    float wsm[4] = {e0 * inv, e1 * inv, e2 * inv, e3 * inv};

    const __half* vb = value + (size_t)b * (HH * WW) * CC + head * DH + di;
    float acc = 0.f;
    #pragma unroll
    for (int p = 0; p < 4; p++) {
        float x = rx * (float)WW + op[p*2+0] - 0.5f;
        float y = ry * (float)HH + op[p*2+1] - 0.5f;
        float x0f = floorf(x), y0f = floorf(y);
        int   x0 = (int)x0f,  y0 = (int)y0f;
        float wx1 = x - x0f, wy1 = y - y0f;
        float wx0 = 1.f - wx1, wy0 = 1.f - wy1;
        float s = 0.f;
        #pragma unroll
        for (int cc = 0; cc < 4; cc++) {
            int xi = x0 + (cc & 1);
            int yi = y0 + (cc >> 1);
            float w = ((cc & 1) ? wx1 : wx0) * ((cc >> 1) ? wy1 : wy0);
            if (xi >= 0 && xi < WW && yi >= 0 && yi < HH)
                s += w * __half2float(vb[(size_t)(yi * WW + xi) * CC]);
        }
        acc += wsm[p] * s;
    }
    oh[(size_t)bq * CC + head * DH + di] = __float2half(acc);
}

// ---------------- launch ----------------
extern "C" void kernel_launch(void* const* d_in, const int* in_sizes, int n_in,
                              void* d_out, int out_size)
{
    const float* query = (const float*)d_in[0];
    const float* refp  = (const float*)d_in[1];
    const float* feat  = (const float*)d_in[2];
    int p = n_in - 18;
    const float* qn_g  = (const float*)d_in[p + 0];
    const float* qn_b  = (const float*)d_in[p + 1];
    const float* fn_g  = (const float*)d_in[p + 2];
    const float* fn_b  = (const float*)d_in[p + 3];
    const float* Wv    = (const float*)d_in[p + 4];
    const float* bv    = (const float*)d_in[p + 5];
    const float* Woff  = (const float*)d_in[p + 6];
    const float* boff  = (const float*)d_in[p + 7];
    const float* Watt  = (const float*)d_in[p + 8];
    const float* batt  = (const float*)d_in[p + 9];
    const float* Wout  = (const float*)d_in[p + 10];
    const float* bout  = (const float*)d_in[p + 11];
    const float* ffn_g = (const float*)d_in[p + 12];
    const float* ffn_b = (const float*)d_in[p + 13];
    const float* W1    = (const float*)d_in[p + 14];
    const float* b1    = (const float*)d_in[p + 15];
    const float* W2    = (const float*)d_in[p + 16];
    const float* b2    = (const float*)d_in[p + 17];
    float* out = (float*)d_out;

    __half *xf, *xq, *val, *s, *hmid, *out16;
    __half *wvt, *wot, *wct, *w1t, *w2t;
    float *offatt, *bcomb, *b1p;
    cudaGetSymbolAddress((void**)&xf, g_xf);
    cudaGetSymbolAddress((void**)&xq, g_xq);
    cudaGetSymbolAddress((void**)&val, g_value);
    cudaGetSymbolAddress((void**)&s, g_s);
    cudaGetSymbolAddress((void**)&hmid, g_hmid);
    cudaGetSymbolAddress((void**)&out16, g_out16);
    cudaGetSymbolAddress((void**)&wvt, g_wvt);
    cudaGetSymbolAddress((void**)&wot, g_wot);
    cudaGetSymbolAddress((void**)&wct, g_wct);
    cudaGetSymbolAddress((void**)&w1t, g_w1t);
    cudaGetSymbolAddress((void**)&w2t, g_w2t);
    cudaGetSymbolAddress((void**)&offatt, g_offatt);
    cudaGetSymbolAddress((void**)&bcomb, g_bcomb);
    cudaGetSymbolAddress((void**)&b1p, g_b1p);

    const int SMEM_GEMM = 3 * 2 * 128 * SSTR * 2;   // 110592 B (3-stage) -> 2 CTAs/SM
    cudaFuncSetAttribute(mma_gemm<4>, cudaFuncAttributeMaxDynamicSharedMemorySize, SMEM_GEMM);
    cudaFuncSetAttribute(mma_gemm<2>, cudaFuncAttributeMaxDynamicSharedMemorySize, SMEM_GEMM);
    cudaFuncSetAttribute(mma_gemm<5>, cudaFuncAttributeMaxDynamicSharedMemorySize, SMEM_GEMM);
    cudaFuncSetAttribute(gemm_pair_kernel, cudaFuncAttributeMaxDynamicSharedMemorySize, SMEM_GEMM);

    // 1. fused prep: coalesced weight transpose + LN(feat) + LN(query)
    prep_kernel<<<409 + 2 * MROWS, 256>>>(feat, query, fn_g, fn_b, qn_g, qn_b, xf, xq,
        Wv, Wout, Woff, Watt, W1, W2, wvt, wot, wct, w1t, w2t,
        boff, batt, b1, bcomb, b1p);

    // 2. fused GEMM pair: value + offsets/logits
    gemm_pair_kernel<<<1024, 256, SMEM_GEMM>>>(xf, wvt, bv, val, xq, wct, bcomb, offatt);

    // 3. softmax + bilinear sampling -> fp16
    sample_kernel<<<MROWS * NHH / 4, 256>>>(val, refp, offatt, s);

    // 4. out16 = fp16(query + samp @ Wout + bout)
    mma_gemm<4><<<dim3(6, 128), 256, SMEM_GEMM>>>(s, wot, bout, query, nullptr,
        nullptr, out16, CC, CC, CC);

    // 5. FFN
    ln_h_kernel<<<MROWS, 256>>>(out16, ffn_g, ffn_b, xf);
    mma_gemm<2><<<dim3(2, 128), 256, SMEM_GEMM>>>(xf, w1t, b1p, nullptr, nullptr,
        nullptr, hmid, CC, HID, HID);
    // 6. out = out16 + GELU(...) @ W2 + b2   (fp32 final)
    mma_gemm<5><<<dim3(6, 128), 256, SMEM_GEMM>>>(hmid, w2t, b2, nullptr, out16,
        out, nullptr, HID, CC, CC);
}

// round 15
// speedup vs baseline: 2.4880x; 1.1618x over previous
#include <cuda_runtime.h>
#include <cuda_fp16.h>
#include <math.h>
#include <cstdint>

// Problem constants
#define B_    4
#define LQ    4096
#define CC    768
#define NHH   12
#define DH    64
#define HH    64
#define WW    64
#define HID   192
#define MROWS (B_*LQ)   // 16384

// ---------------- scratch ----------------
__device__ __align__(16) __half g_xf[MROWS*CC];                     // LN out fp16 (reused)
__device__ __align__(16) __half g_xq[MROWS*CC];                     // LN(query) fp16
__device__ __align__(16) __half g_value[MROWS*CC];                  // value fp16
__device__ __align__(16) float  g_offatt[MROWS*192];                // off(96)+logits(48)+pad
__device__ __align__(16) __half g_s[MROWS*CC];                      // sampled fp16
__device__ __align__(16) __half g_hmid[MROWS*HID];                  // FFN hidden fp16
__device__ __align__(16) __half g_out16[MROWS*CC];                  // step4 result fp16
// transposed weights [Npad][K] fp16
__device__ __align__(16) __half g_wvt[CC*CC];
__device__ __align__(16) __half g_wot[CC*CC];
__device__ __align__(16) __half g_wct[256*CC];
__device__ __align__(16) __half g_w1t[256*CC];
__device__ __align__(16) __half g_w2t[CC*HID];
__device__ float g_bcomb[256], g_b1p[256];

// ---------------- LN bodies ----------------
__device__ __forceinline__ void ln_reduce_and_store(float4 v, const float* gamma,
                                                    const float* beta, __half* oh, int row)
{
    int t = threadIdx.x;
    float s  = v.x + v.y + v.z + v.w;
    float s2 = v.x*v.x + v.y*v.y + v.z*v.z + v.w*v.w;
    #pragma unroll
    for (int o = 16; o; o >>= 1) {
        s  += __shfl_xor_sync(0xffffffffu, s,  o);
        s2 += __shfl_xor_sync(0xffffffffu, s2, o);
    }
    __shared__ float ssum[8], ssum2[8];
    int w = t >> 5;
    if ((t & 31) == 0) { ssum[w] = s; ssum2[w] = s2; }
    __syncthreads();
    float S = 0.f, S2 = 0.f;
    #pragma unroll
    for (int i = 0; i < 8; i++) { S += ssum[i]; S2 += ssum2[i]; }
    float mean = S * (1.0f / CC);
    float var  = S2 * (1.0f / CC) - mean * mean;
    float inv  = rsqrtf(var + 1e-5f);
    if (t < 192) {
        float4 gg = *reinterpret_cast<const float4*>(gamma + t * 4);
        float4 bb = *reinterpret_cast<const float4*>(beta  + t * 4);
        __half2 h0 = __floats2half2_rn((v.x - mean) * inv * gg.x + bb.x,
                                       (v.y - mean) * inv * gg.y + bb.y);
        __half2 h1 = __floats2half2_rn((v.z - mean) * inv * gg.z + bb.z,
                                       (v.w - mean) * inv * gg.w + bb.w);
        *reinterpret_cast<__half2*>(oh + (size_t)row * CC + t * 4)     = h0;
        *reinterpret_cast<__half2*>(oh + (size_t)row * CC + t * 4 + 2) = h1;
    }
}

__device__ __forceinline__ void ln_row_f(const float* __restrict__ in,
                                         const float* gamma, const float* beta,
                                         __half* oh, int row)
{
    int t = threadIdx.x;
    float4 v = make_float4(0.f, 0.f, 0.f, 0.f);
    if (t < 192) v = *reinterpret_cast<const float4*>(in + (size_t)row * CC + t * 4);
    ln_reduce_and_store(v, gamma, beta, oh, row);
}

__device__ __forceinline__ void ln_row_h(const __half* __restrict__ in,
                                         const float* gamma, const float* beta,
                                         __half* oh, int row)
{
    int t = threadIdx.x;
    float4 v = make_float4(0.f, 0.f, 0.f, 0.f);
    if (t < 192) {
        __half2 a = *reinterpret_cast<const __half2*>(in + (size_t)row * CC + t * 4);
        __half2 b = *reinterpret_cast<const __half2*>(in + (size_t)row * CC + t * 4 + 2);
        float2 fa = __half22float2(a), fb = __half22float2(b);
        v = make_float4(fa.x, fa.y, fb.x, fb.y);
    }
    ln_reduce_and_store(v, gamma, beta, oh, row);
}

// ---------------- fused prep: coalesced weight transpose tiles + both LNs ------
__global__ __launch_bounds__(256) void prep_kernel(
    const float* __restrict__ feat, const float* __restrict__ query,
    const float* __restrict__ fn_g, const float* __restrict__ fn_b,
    const float* __restrict__ qn_g, const float* __restrict__ qn_b,
    __half* __restrict__ xf, __half* __restrict__ xq,
    const float* __restrict__ Wv, const float* __restrict__ Wout,
    const float* __restrict__ Woff, const float* __restrict__ Watt,
    const float* __restrict__ W1, const float* __restrict__ W2,
    __half* wvt, __half* wot, __half* wct, __half* w1t, __half* w2t,
    const float* boff, const float* batt, const float* b1,
    float* bcomb, float* b1p)
{
    int blk = blockIdx.x;
    if (blk >= 409) {
        int row = blk - 409;
        if (row < MROWS) ln_row_f(feat, fn_g, fn_b, xf, row);
        else             ln_row_f(query, qn_g, qn_b, xq, row - MROWS);
        return;
    }
    if (blk == 408) {
        int i = threadIdx.x;
        bcomb[i] = (i < 96) ? boff[i] : (i < 144 ? batt[i - 96] : 0.0f);
        b1p[i]   = (i < 192) ? b1[i] : 0.0f;
        return;
    }
    int seg, rel, ntx, K, Npad;
    __half* dst;
    if (blk < 144)      { seg=0; rel=blk;     ntx=12; K=CC;  Npad=CC;  dst=g_wvt; }
    else if (blk < 288) { seg=1; rel=blk-144; ntx=12; K=CC;  Npad=CC;  dst=g_wot; }
    else if (blk < 324) { seg=2; rel=blk-288; ntx=3;  K=CC;  Npad=160; dst=g_wct; }
    else if (blk < 372) { seg=3; rel=blk-324; ntx=4;  K=CC;  Npad=256; dst=g_w1t; }
    else                { seg=4; rel=blk-372; ntx=12; K=HID; Npad=CC;  dst=g_w2t; }
    int ty = rel / ntx, tx = rel % ntx;
    int k0 = ty * 64, n0 = tx * 64;

    __shared__ __half tile[64][66];
    int tid = threadIdx.x;
    #pragma unroll
    for (int it = 0; it < 16; it++) {
        int idx = it * 256 + tid;
        int kk = idx >> 6, nn = idx & 63;
        int k = k0 + kk, n = n0 + nn;
        float v = 0.0f;
        if (seg == 0)      { v = Wv  [(size_t)k * CC  + n]; }
        else if (seg == 1) { v = Wout[(size_t)k * CC  + n]; }
        else if (seg == 2) {
            if (n < 96)       v = Woff[(size_t)k * 96  + n];
            else if (n < 144) v = Watt[(size_t)k * 48  + (n - 96)];
        }
        else if (seg == 3) { if (n < HID) v = W1[(size_t)k * HID + n]; }
        else               { v = W2  [(size_t)k * CC  + n]; }
        tile[kk][nn] = __float2half(v);
    }
    __syncthreads();
    #pragma unroll
    for (int it = 0; it < 16; it++) {
        int idx = it * 256 + tid;
        int nn = idx >> 6, kk = idx & 63;
        int n = n0 + nn;
        if (n < Npad)
            dst[(size_t)n * K + k0 + kk] = tile[kk][nn];
    }
}

__global__ __launch_bounds__(256) void ln_h_kernel(const __half* __restrict__ in,
                                                   const float* __restrict__ gamma,
                                                   const float* __restrict__ beta,
                                                   __half* __restrict__ oh)
{
    ln_row_h(in, gamma, beta, oh, blockIdx.x);
}

// ---------------- GEMM core: BK=64, 3-stage, 2 CTAs/SM, reg double-buffer ----
#define SSTR 72  // smem row stride in halfs (64 + 8 pad)

__device__ __forceinline__ void mma16816(float* d, const uint32_t* a, const uint32_t* b) {
    asm volatile(
        "mma.sync.aligned.m16n8k16.row.col.f32.f16.f16.f32 "
        "{%0,%1,%2,%3}, {%4,%5,%6,%7}, {%8,%9}, {%0,%1,%2,%3};"
        : "+f"(d[0]), "+f"(d[1]), "+f"(d[2]), "+f"(d[3])
        : "r"(a[0]), "r"(a[1]), "r"(a[2]), "r"(a[3]), "r"(b[0]), "r"(b[1]));
}
#define LDSM_X4(R0,R1,R2,R3,ADDR) \
    asm volatile("ldmatrix.sync.aligned.m8n8.x4.shared.b16 {%0,%1,%2,%3}, [%4];" \
        : "=r"(R0), "=r"(R1), "=r"(R2), "=r"(R3) : "r"(ADDR))
#define CPA16(DST,SRC) \
    asm volatile("cp.async.cg.shared.global [%0], [%1], 16;" :: "r"(DST), "l"(SRC) : "memory")
#define CPC() asm volatile("cp.async.commit_group;" ::: "memory")
#define CPW1() asm volatile("cp.async.wait_group 1;" ::: "memory")
#define CPW0() asm volatile("cp.async.wait_group 0;" ::: "memory")

// EPI: 0 bias->fp32; 2 bias+GELU->fp16; 3 bias->fp16;
//      4 bias+res(f32)->fp16; 5 bias+res(f16)->fp32
template<int EPI>
__device__ __forceinline__ void gemm_body(
    const __half* __restrict__ A, const __half* __restrict__ B,
    const float* __restrict__ bias, const float* __restrict__ res,
    const __half* __restrict__ resh,
    float* __restrict__ Cf, __half* __restrict__ Ch,
    int K, int ldc, int Ncols, int m0, int n0, __half* sm)
{
    const int ARR = 128 * SSTR;
    const int STG = 2 * ARR;

    const int tid = threadIdx.x, lane = tid & 31, wid = tid >> 5;
    const int wm = wid & 1, wn = wid >> 1;

    const uint32_t smb = (uint32_t)__cvta_generic_to_shared(sm);

    int srow[4], sg[4];
    #pragma unroll
    for (int i = 0; i < 4; i++) { int idx = i * 256 + tid; srow[i] = idx >> 3; sg[i] = idx & 7; }

    auto issue = [&](int c, int s) {
        const int kc = c * 64;
        #pragma unroll
        for (int i = 0; i < 4; i++) {
            int row = srow[i], g = sg[i];
            size_t ga = (size_t)(m0 + row) * K + kc + g * 8;
            size_t gb = (size_t)(n0 + row) * K + kc + g * 8;
            uint32_t so = smb + (uint32_t)(s * STG + row * SSTR + g * 8) * 2;
            CPA16(so + 0 * ARR * 2, A + ga);
            CPA16(so + 1 * ARR * 2, B + gb);
        }
    };

    float acc[4][4][4];
    #pragma unroll
    for (int i = 0; i < 4; i++)
        #pragma unroll
        for (int j = 0; j < 4; j++)
            #pragma unroll
            for (int q = 0; q < 4; q++) acc[i][j][q] = 0.f;

    const int a_lrow = lane & 15, a_lcol = (lane >> 4) * 8;
    const int b_lrow = (lane & 7) + ((lane >> 4) * 8), b_lcol = ((lane >> 3) & 1) * 8;

    uint32_t bf[2][4][2], af[2][4][4];

    auto load_frags = [&](uint32_t baseA, uint32_t baseB, int kk, int buf) {
        const int kb = kk * 16;
        #pragma unroll
        for (int nn = 0; nn < 2; nn++) {
            uint32_t off = (uint32_t)((wn * 32 + nn * 16 + b_lrow) * SSTR + kb + b_lcol) * 2;
            LDSM_X4(bf[buf][nn*2][0], bf[buf][nn*2][1], bf[buf][nn*2+1][0], bf[buf][nn*2+1][1], baseB + off);
        }
        #pragma unroll
        for (int mi = 0; mi < 4; mi++) {
            uint32_t off = (uint32_t)((wm * 64 + mi * 16 + a_lrow) * SSTR + kb + a_lcol) * 2;
            LDSM_X4(af[buf][mi][0], af[buf][mi][1], af[buf][mi][2], af[buf][mi][3], baseA + off);
        }
    };

    const int KC = K >> 6;
    issue(0, 0); CPC();
    issue(1, 1); CPC();

    for (int c = 0; c < KC; c++) {
        if (c == KC - 1) { CPW0(); } else { CPW1(); }
        __syncthreads();
        if (c + 2 < KC) { issue(c + 2, (c + 2) % 3); CPC(); }

        const int st = (c % 3) * STG;
        const uint32_t baseA = smb + (uint32_t)(st + 0 * ARR) * 2;
        const uint32_t baseB = smb + (uint32_t)(st + 1 * ARR) * 2;

        load_frags(baseA, baseB, 0, 0);
        #pragma unroll
        for (int kk = 0; kk < 4; kk++) {
            int cur = kk & 1;
            if (kk < 3) load_frags(baseA, baseB, kk + 1, cur ^ 1);
            #pragma unroll
            for (int mi = 0; mi < 4; mi++)
                #pragma unroll
                for (int ni = 0; ni < 4; ni++)
                    mma16816(acc[mi][ni], af[cur][mi], bf[cur][ni]);
        }
    }

    const int qrow = lane >> 2, qk = (lane & 3) * 2;
    #pragma unroll
    for (int mi = 0; mi < 4; mi++) {
        #pragma unroll
        for (int ni = 0; ni < 4; ni++) {
            int c0 = n0 + wn * 32 + ni * 8 + qk;
            if (c0 >= Ncols) continue;
            int r0 = m0 + wm * 64 + mi * 16 + qrow;
            float b0 = bias[c0], b1v = bias[c0 + 1];
            #pragma unroll
            for (int h = 0; h < 2; h++) {
                int m = r0 + h * 8;
                float v0 = acc[mi][ni][h*2+0] + b0;
                float v1 = acc[mi][ni][h*2+1] + b1v;
                if (EPI == 4) {
                    float2 rr = *reinterpret_cast<const float2*>(res + (size_t)m * ldc + c0);
                    v0 += rr.x; v1 += rr.y;
                }
                if (EPI == 5) {
                    __half2 rr = *reinterpret_cast<const __half2*>(resh + (size_t)m * ldc + c0);
                    float2 fr = __half22float2(rr);
                    v0 += fr.x; v1 += fr.y;
                }
                if (EPI == 2) {
                    v0 = 0.5f * v0 * (1.0f + erff(v0 * 0.70710678118654752f));
                    v1 = 0.5f * v1 * (1.0f + erff(v1 * 0.70710678118654752f));
                }
                if (EPI == 2 || EPI == 3 || EPI == 4) {
                    *reinterpret_cast<__half2*>(Ch + (size_t)m * ldc + c0) =
                        __floats2half2_rn(v0, v1);
                } else {
                    *reinterpret_cast<float2*>(Cf + (size_t)m * ldc + c0) =
                        make_float2(v0, v1);
                }
            }
        }
    }
}

template<int EPI>
__global__ __launch_bounds__(256, 2) void mma_gemm(
    const __half* __restrict__ A, const __half* __restrict__ B,
    const float* __restrict__ bias, const float* __restrict__ res,
    const __half* __restrict__ resh,
    float* __restrict__ Cf, __half* __restrict__ Ch,
    int K, int ldc, int Ncols)
{
    extern __shared__ __half sm[];
    gemm_body<EPI>(A, B, bias, res, resh, Cf, Ch, K, ldc, Ncols,
                   blockIdx.y * 128, blockIdx.x * 128, sm);
}

// fused pair: value GEMM (768 CTAs) + offset/attention GEMM (256 CTAs)
__global__ __launch_bounds__(256, 2) void gemm_pair_kernel(
    const __half* __restrict__ xf, const __half* __restrict__ wvt,
    const float* __restrict__ bv, __half* __restrict__ val,
    const __half* __restrict__ xq, const __half* __restrict__ wct,
    const float* __restrict__ bcomb, float* __restrict__ offatt)
{
    extern __shared__ __half sm[];
    int t = blockIdx.x;
    if (t < 768) {
        gemm_body<3>(xf, wvt, bv, nullptr, nullptr, nullptr, val,
                     CC, CC, CC, (t / 6) * 128, (t % 6) * 128, sm);
    } else {
        int t2 = t - 768;
        gemm_body<0>(xq, wct, bcomb, nullptr, nullptr, offatt, nullptr,
                     CC, 192, 144, (t2 / 2) * 128, (t2 % 2) * 128, sm);
    }
}

// ---------------- sampling: one warp per (bq,head), half2 lanes ----------------
__global__ __launch_bounds__(256) void sample_kernel(
    const __half* __restrict__ value,
    const float* __restrict__ refp,
    const float* __restrict__ offatt,
    __half* __restrict__ oh)
{
    int gid = blockIdx.x * 8 + (threadIdx.x >> 5);   // over B*Lq*NH
    int lane = threadIdx.x & 31;
    int head = gid % NHH;
    int bq   = gid / NHH;
    int b    = bq / LQ;

    const float* rp = refp + (size_t)bq * 2;
    float rx = rp[0], ry = rp[1];
    const float* op = offatt + (size_t)bq * 192 + head * 8;
    const float* lp = offatt + (size_t)bq * 192 + 96 + head * 4;

    float l0 = lp[0], l1 = lp[1], l2 = lp[2], l3 = lp[3];
    float mx = fmaxf(fmaxf(l0, l1), fmaxf(l2, l3));
    float e0 = expf(l0 - mx), e1 = expf(l1 - mx), e2 = expf(l2 - mx), e3 = expf(l3 - mx);
    float inv = 1.0f / (e0 + e1 + e2 + e3);
    float wsm[4] = {e0 * inv, e1 * inv, e2 * inv, e3 * inv};

    const __half* vb = value + (size_t)b * (HH * WW) * CC + head * DH + lane * 2;
    float a0 = 0.f, a1 = 0.f;
    #pragma unroll
    for (int p = 0; p < 4; p++) {
        float x = rx * (float)WW + op[p*2+0] - 0.5f;
        float y = ry * (float)HH + op[p*2+1] - 0.5f;
        float x0f = floorf(x), y0f = floorf(y);
        int   x0 = (int)x0f,  y0 = (int)y0f;
        float wx1 = x - x0f, wy1 = y - y0f;
        float wx0 = 1.f - wx1, wy0 = 1.f - wy1;
        float s0 = 0.f, s1 = 0.f;
        #pragma unroll
        for (int cc = 0; cc < 4; cc++) {
            int xi = x0 + (cc & 1);
            int yi = y0 + (cc >> 1);
            float w = ((cc & 1) ? wx1 : wx0) * ((cc >> 1) ? wy1 : wy0);
            if (xi >= 0 && xi < WW && yi >= 0 && yi < HH) {
                __half2 hv = *reinterpret_cast<const __half2*>(vb + (size_t)(yi * WW + xi) * CC);
                float2 fv = __half22float2(hv);
                s0 += w * fv.x;
                s1 += w * fv.y;
            }
        }
        a0 += wsm[p] * s0;
        a1 += wsm[p] * s1;
    }
    *reinterpret_cast<__half2*>(oh + (size_t)bq * CC + head * DH + lane * 2) =
        __floats2half2_rn(a0, a1);
}

// ---------------- launch ----------------
extern "C" void kernel_launch(void* const* d_in, const int* in_sizes, int n_in,
                              void* d_out, int out_size)
{
    const float* query = (const float*)d_in[0];
    const float* refp  = (const float*)d_in[1];
    const float* feat  = (const float*)d_in[2];
    int p = n_in - 18;
    const float* qn_g  = (const float*)d_in[p + 0];
    const float* qn_b  = (const float*)d_in[p + 1];
    const float* fn_g  = (const float*)d_in[p + 2];
    const float* fn_b  = (const float*)d_in[p + 3];
    const float* Wv    = (const float*)d_in[p + 4];
    const float* bv    = (const float*)d_in[p + 5];
    const float* Woff  = (const float*)d_in[p + 6];
    const float* boff  = (const float*)d_in[p + 7];
    const float* Watt  = (const float*)d_in[p + 8];
    const float* batt  = (const float*)d_in[p + 9];
    const float* Wout  = (const float*)d_in[p + 10];
    const float* bout  = (const float*)d_in[p + 11];
    const float* ffn_g = (const float*)d_in[p + 12];
    const float* ffn_b = (const float*)d_in[p + 13];
    const float* W1    = (const float*)d_in[p + 14];
    const float* b1    = (const float*)d_in[p + 15];
    const float* W2    = (const float*)d_in[p + 16];
    const float* b2    = (const float*)d_in[p + 17];
    float* out = (float*)d_out;

    __half *xf, *xq, *val, *s, *hmid, *out16;
    __half *wvt, *wot, *wct, *w1t, *w2t;
    float *offatt, *bcomb, *b1p;
    cudaGetSymbolAddress((void**)&xf, g_xf);
    cudaGetSymbolAddress((void**)&xq, g_xq);
    cudaGetSymbolAddress((void**)&val, g_value);
    cudaGetSymbolAddress((void**)&s, g_s);
    cudaGetSymbolAddress((void**)&hmid, g_hmid);
    cudaGetSymbolAddress((void**)&out16, g_out16);
    cudaGetSymbolAddress((void**)&wvt, g_wvt);
    cudaGetSymbolAddress((void**)&wot, g_wot);
    cudaGetSymbolAddress((void**)&wct, g_wct);
    cudaGetSymbolAddress((void**)&w1t, g_w1t);
    cudaGetSymbolAddress((void**)&w2t, g_w2t);
    cudaGetSymbolAddress((void**)&offatt, g_offatt);
    cudaGetSymbolAddress((void**)&bcomb, g_bcomb);
    cudaGetSymbolAddress((void**)&b1p, g_b1p);

    const int SMEM_GEMM = 3 * 2 * 128 * SSTR * 2;   // 110592 B (3-stage) -> 2 CTAs/SM
    cudaFuncSetAttribute(mma_gemm<4>, cudaFuncAttributeMaxDynamicSharedMemorySize, SMEM_GEMM);
    cudaFuncSetAttribute(mma_gemm<2>, cudaFuncAttributeMaxDynamicSharedMemorySize, SMEM_GEMM);
    cudaFuncSetAttribute(mma_gemm<5>, cudaFuncAttributeMaxDynamicSharedMemorySize, SMEM_GEMM);
    cudaFuncSetAttribute(gemm_pair_kernel, cudaFuncAttributeMaxDynamicSharedMemorySize, SMEM_GEMM);

    // 1. fused prep: coalesced weight transpose + LN(feat) + LN(query)
    prep_kernel<<<409 + 2 * MROWS, 256>>>(feat, query, fn_g, fn_b, qn_g, qn_b, xf, xq,
        Wv, Wout, Woff, Watt, W1, W2, wvt, wot, wct, w1t, w2t,
        boff, batt, b1, bcomb, b1p);

    // 2. fused GEMM pair: value + offsets/logits
    gemm_pair_kernel<<<1024, 256, SMEM_GEMM>>>(xf, wvt, bv, val, xq, wct, bcomb, offatt);

    // 3. softmax + bilinear sampling (warp per (bq,head), half2 lanes)
    sample_kernel<<<MROWS * NHH / 8, 256>>>(val, refp, offatt, s);

    // 4. out16 = fp16(query + samp @ Wout + bout)
    mma_gemm<4><<<dim3(6, 128), 256, SMEM_GEMM>>>(s, wot, bout, query, nullptr,
        nullptr, out16, CC, CC, CC);

    // 5. FFN
    ln_h_kernel<<<MROWS, 256>>>(out16, ffn_g, ffn_b, xf);
    mma_gemm<2><<<dim3(2, 128), 256, SMEM_GEMM>>>(xf, w1t, b1p, nullptr, nullptr,
        nullptr, hmid, CC, HID, HID);
    // 6. out = out16 + GELU(...) @ W2 + b2   (fp32 final)
    mma_gemm<5><<<dim3(6, 128), 256, SMEM_GEMM>>>(hmid, w2t, b2, nullptr, out16,
        out, nullptr, HID, CC, CC);
}

// round 16
// speedup vs baseline: 2.6290x; 1.0566x over previous
#include <cuda_runtime.h>
#include <cuda_fp16.h>
#include <math.h>
#include <cstdint>

// Problem constants
#define B_    4
#define LQ    4096
#define CC    768
#define NHH   12
#define DH    64
#define HH    64
#define WW    64
#define HID   192
#define MROWS (B_*LQ)   // 16384

// ---------------- scratch ----------------
__device__ __align__(16) __half g_xf[MROWS*CC];                     // LN out fp16 (reused)
__device__ __align__(16) __half g_xq[MROWS*CC];                     // LN(query) fp16
__device__ __align__(16) __half g_value[MROWS*CC];                  // value fp16
__device__ __align__(16) float  g_offatt[MROWS*192];                // off(96)+logits(48)+pad
__device__ __align__(16) __half g_s[MROWS*CC];                      // sampled fp16
__device__ __align__(16) __half g_hmid[MROWS*HID];                  // FFN hidden fp16
__device__ __align__(16) __half g_out16[MROWS*CC];                  // step4 result fp16
// transposed weights [Npad][K] fp16
__device__ __align__(16) __half g_wvt[CC*CC];
__device__ __align__(16) __half g_wot[CC*CC];
__device__ __align__(16) __half g_wct[256*CC];
__device__ __align__(16) __half g_w1t[256*CC];
__device__ __align__(16) __half g_w2t[CC*HID];
__device__ float g_bcomb[256], g_b1p[256];

// ---------------- warp-per-row LN (no smem, shfl-only reduction) ----------------
// IN_HALF: input dtype. Each warp: lane loads 6 float4 (192 f4 per row / 32 lanes).
template<bool IN_HALF>
__device__ __forceinline__ void ln_row_warp(const void* __restrict__ in,
                                            const float* __restrict__ gamma,
                                            const float* __restrict__ beta,
                                            __half* __restrict__ oh, int row)
{
    int lane = threadIdx.x & 31;
    float v[24];
    if (IN_HALF) {
        const __half* src = (const __half*)in + (size_t)row * CC;
        #pragma unroll
        for (int i = 0; i < 6; i++) {
            int c = (lane + i * 32) * 4;
            __half2 a = *reinterpret_cast<const __half2*>(src + c);
            __half2 b = *reinterpret_cast<const __half2*>(src + c + 2);
            float2 fa = __half22float2(a), fb = __half22float2(b);
            v[i*4+0] = fa.x; v[i*4+1] = fa.y; v[i*4+2] = fb.x; v[i*4+3] = fb.y;
        }
    } else {
        const float* src = (const float*)in + (size_t)row * CC;
        #pragma unroll
        for (int i = 0; i < 6; i++) {
            float4 f = *reinterpret_cast<const float4*>(src + (lane + i * 32) * 4);
            v[i*4+0] = f.x; v[i*4+1] = f.y; v[i*4+2] = f.z; v[i*4+3] = f.w;
        }
    }
    float s = 0.f, s2 = 0.f;
    #pragma unroll
    for (int i = 0; i < 24; i++) { s += v[i]; s2 += v[i]*v[i]; }
    #pragma unroll
    for (int o = 16; o; o >>= 1) {
        s  += __shfl_xor_sync(0xffffffffu, s,  o);
        s2 += __shfl_xor_sync(0xffffffffu, s2, o);
    }
    float mean = s * (1.0f / CC);
    float var  = s2 * (1.0f / CC) - mean * mean;
    float inv  = rsqrtf(var + 1e-5f);
    __half* dst = oh + (size_t)row * CC;
    #pragma unroll
    for (int i = 0; i < 6; i++) {
        int c = (lane + i * 32) * 4;
        float4 gg = *reinterpret_cast<const float4*>(gamma + c);
        float4 bb = *reinterpret_cast<const float4*>(beta  + c);
        __half2 h0 = __floats2half2_rn((v[i*4+0] - mean) * inv * gg.x + bb.x,
                                       (v[i*4+1] - mean) * inv * gg.y + bb.y);
        __half2 h1 = __floats2half2_rn((v[i*4+2] - mean) * inv * gg.z + bb.z,
                                       (v[i*4+3] - mean) * inv * gg.w + bb.w);
        *reinterpret_cast<__half2*>(dst + c)     = h0;
        *reinterpret_cast<__half2*>(dst + c + 2) = h1;
    }
}

// ---------------- fused prep: transpose tiles + both LNs (warp-per-row) --------
// blocks [0,408): 64x64 transpose tiles; 408: bias; [409, 409+4096): LN rows (8 warps/blk)
__global__ __launch_bounds__(256) void prep_kernel(
    const float* __restrict__ feat, const float* __restrict__ query,
    const float* __restrict__ fn_g, const float* __restrict__ fn_b,
    const float* __restrict__ qn_g, const float* __restrict__ qn_b,
    __half* __restrict__ xf, __half* __restrict__ xq,
    const float* __restrict__ Wv, const float* __restrict__ Wout,
    const float* __restrict__ Woff, const float* __restrict__ Watt,
    const float* __restrict__ W1, const float* __restrict__ W2,
    __half* wvt, __half* wot, __half* wct, __half* w1t, __half* w2t,
    const float* boff, const float* batt, const float* b1,
    float* bcomb, float* b1p)
{
    int blk = blockIdx.x;
    if (blk >= 409) {
        // 8 warps per block, each one LN row; 32768 rows total
        int row = (blk - 409) * 8 + (threadIdx.x >> 5);
        if (row < MROWS) ln_row_warp<false>(feat, fn_g, fn_b, xf, row);
        else             ln_row_warp<false>(query, qn_g, qn_b, xq, row - MROWS);
        return;
    }
    if (blk == 408) {
        int i = threadIdx.x;
        bcomb[i] = (i < 96) ? boff[i] : (i < 144 ? batt[i - 96] : 0.0f);
        b1p[i]   = (i < 192) ? b1[i] : 0.0f;
        return;
    }
    int seg, rel, ntx, K, Npad;
    __half* dst;
    if (blk < 144)      { seg=0; rel=blk;     ntx=12; K=CC;  Npad=CC;  dst=g_wvt; }
    else if (blk < 288) { seg=1; rel=blk-144; ntx=12; K=CC;  Npad=CC;  dst=g_wot; }
    else if (blk < 324) { seg=2; rel=blk-288; ntx=3;  K=CC;  Npad=160; dst=g_wct; }
    else if (blk < 372) { seg=3; rel=blk-324; ntx=4;  K=CC;  Npad=256; dst=g_w1t; }
    else                { seg=4; rel=blk-372; ntx=12; K=HID; Npad=CC;  dst=g_w2t; }
    int ty = rel / ntx, tx = rel % ntx;
    int k0 = ty * 64, n0 = tx * 64;

    __shared__ __half tile[64][66];
    int tid = threadIdx.x;
    #pragma unroll
    for (int it = 0; it < 16; it++) {
        int idx = it * 256 + tid;
        int kk = idx >> 6, nn = idx & 63;
        int k = k0 + kk, n = n0 + nn;
        float v = 0.0f;
        if (seg == 0)      { v = Wv  [(size_t)k * CC  + n]; }
        else if (seg == 1) { v = Wout[(size_t)k * CC  + n]; }
        else if (seg == 2) {
            if (n < 96)       v = Woff[(size_t)k * 96  + n];
            else if (n < 144) v = Watt[(size_t)k * 48  + (n - 96)];
        }
        else if (seg == 3) { if (n < HID) v = W1[(size_t)k * HID + n]; }
        else               { v = W2  [(size_t)k * CC  + n]; }
        tile[kk][nn] = __float2half(v);
    }
    __syncthreads();
    // write phase: half2 per thread, consecutive threads -> consecutive k pairs
    #pragma unroll
    for (int it = 0; it < 8; it++) {
        int idx = it * 256 + tid;
        int nn = idx >> 5, kh = idx & 31;     // kh: half2 index along k
        int n = n0 + nn;
        if (n < Npad) {
            __half2 hv = __halves2half2(tile[kh*2][nn], tile[kh*2+1][nn]);
            *reinterpret_cast<__half2*>(dst + (size_t)n * K + k0 + kh * 2) = hv;
        }
    }
}

// FFN LN: warp per row, 8 rows/block
__global__ __launch_bounds__(256) void ln_h_kernel(const __half* __restrict__ in,
                                                   const float* __restrict__ gamma,
                                                   const float* __restrict__ beta,
                                                   __half* __restrict__ oh)
{
    int row = blockIdx.x * 8 + (threadIdx.x >> 5);
    ln_row_warp<true>(in, gamma, beta, oh, row);
}

// ---------------- GEMM core: BK=64, 3-stage, 2 CTAs/SM, reg double-buffer ----
#define SSTR 72  // smem row stride in halfs (64 + 8 pad)

__device__ __forceinline__ void mma16816(float* d, const uint32_t* a, const uint32_t* b) {
    asm volatile(
        "mma.sync.aligned.m16n8k16.row.col.f32.f16.f16.f32 "
        "{%0,%1,%2,%3}, {%4,%5,%6,%7}, {%8,%9}, {%0,%1,%2,%3};"
        : "+f"(d[0]), "+f"(d[1]), "+f"(d[2]), "+f"(d[3])
        : "r"(a[0]), "r"(a[1]), "r"(a[2]), "r"(a[3]), "r"(b[0]), "r"(b[1]));
}
#define LDSM_X4(R0,R1,R2,R3,ADDR) \
    asm volatile("ldmatrix.sync.aligned.m8n8.x4.shared.b16 {%0,%1,%2,%3}, [%4];" \
        : "=r"(R0), "=r"(R1), "=r"(R2), "=r"(R3) : "r"(ADDR))
#define CPA16(DST,SRC) \
    asm volatile("cp.async.cg.shared.global [%0], [%1], 16;" :: "r"(DST), "l"(SRC) : "memory")
#define CPC() asm volatile("cp.async.commit_group;" ::: "memory")
#define CPW1() asm volatile("cp.async.wait_group 1;" ::: "memory")
#define CPW0() asm volatile("cp.async.wait_group 0;" ::: "memory")

// EPI: 0 bias->fp32; 2 bias+GELU->fp16; 3 bias->fp16;
//      4 bias+res(f32)->fp16; 5 bias+res(f16)->fp32
template<int EPI>
__device__ __forceinline__ void gemm_body(
    const __half* __restrict__ A, const __half* __restrict__ B,
    const float* __restrict__ bias, const float* __restrict__ res,
    const __half* __restrict__ resh,
    float* __restrict__ Cf, __half* __restrict__ Ch,
    int K, int ldc, int Ncols, int m0, int n0, __half* sm)
{
    const int ARR = 128 * SSTR;
    const int STG = 2 * ARR;

    const int tid = threadIdx.x, lane = tid & 31, wid = tid >> 5;
    const int wm = wid & 1, wn = wid >> 1;

    const uint32_t smb = (uint32_t)__cvta_generic_to_shared(sm);

    int srow[4], sg[4];
    #pragma unroll
    for (int i = 0; i < 4; i++) { int idx = i * 256 + tid; srow[i] = idx >> 3; sg[i] = idx & 7; }

    auto issue = [&](int c, int s) {
        const int kc = c * 64;
        #pragma unroll
        for (int i = 0; i < 4; i++) {
            int row = srow[i], g = sg[i];
            size_t ga = (size_t)(m0 + row) * K + kc + g * 8;
            size_t gb = (size_t)(n0 + row) * K + kc + g * 8;
            uint32_t so = smb + (uint32_t)(s * STG + row * SSTR + g * 8) * 2;
            CPA16(so + 0 * ARR * 2, A + ga);
            CPA16(so + 1 * ARR * 2, B + gb);
        }
    };

    float acc[4][4][4];
    #pragma unroll
    for (int i = 0; i < 4; i++)
        #pragma unroll
        for (int j = 0; j < 4; j++)
            #pragma unroll
            for (int q = 0; q < 4; q++) acc[i][j][q] = 0.f;

    const int a_lrow = lane & 15, a_lcol = (lane >> 4) * 8;
    const int b_lrow = (lane & 7) + ((lane >> 4) * 8), b_lcol = ((lane >> 3) & 1) * 8;

    uint32_t bf[2][4][2], af[2][4][4];

    auto load_frags = [&](uint32_t baseA, uint32_t baseB, int kk, int buf) {
        const int kb = kk * 16;
        #pragma unroll
        for (int nn = 0; nn < 2; nn++) {
            uint32_t off = (uint32_t)((wn * 32 + nn * 16 + b_lrow) * SSTR + kb + b_lcol) * 2;
            LDSM_X4(bf[buf][nn*2][0], bf[buf][nn*2][1], bf[buf][nn*2+1][0], bf[buf][nn*2+1][1], baseB + off);
        }
        #pragma unroll
        for (int mi = 0; mi < 4; mi++) {
            uint32_t off = (uint32_t)((wm * 64 + mi * 16 + a_lrow) * SSTR + kb + a_lcol) * 2;
            LDSM_X4(af[buf][mi][0], af[buf][mi][1], af[buf][mi][2], af[buf][mi][3], baseA + off);
        }
    };

    const int KC = K >> 6;
    issue(0, 0); CPC();
    issue(1, 1); CPC();

    for (int c = 0; c < KC; c++) {
        if (c == KC - 1) { CPW0(); } else { CPW1(); }
        __syncthreads();
        if (c + 2 < KC) { issue(c + 2, (c + 2) % 3); CPC(); }

        const int st = (c % 3) * STG;
        const uint32_t baseA = smb + (uint32_t)(st + 0 * ARR) * 2;
        const uint32_t baseB = smb + (uint32_t)(st + 1 * ARR) * 2;

        load_frags(baseA, baseB, 0, 0);
        #pragma unroll
        for (int kk = 0; kk < 4; kk++) {
            int cur = kk & 1;
            if (kk < 3) load_frags(baseA, baseB, kk + 1, cur ^ 1);
            #pragma unroll
            for (int mi = 0; mi < 4; mi++)
                #pragma unroll
                for (int ni = 0; ni < 4; ni++)
                    mma16816(acc[mi][ni], af[cur][mi], bf[cur][ni]);
        }
    }

    const int qrow = lane >> 2, qk = (lane & 3) * 2;
    #pragma unroll
    for (int mi = 0; mi < 4; mi++) {
        #pragma unroll
        for (int ni = 0; ni < 4; ni++) {
            int c0 = n0 + wn * 32 + ni * 8 + qk;
            if (c0 >= Ncols) continue;
            int r0 = m0 + wm * 64 + mi * 16 + qrow;
            float b0 = bias[c0], b1v = bias[c0 + 1];
            #pragma unroll
            for (int h = 0; h < 2; h++) {
                int m = r0 + h * 8;
                float v0 = acc[mi][ni][h*2+0] + b0;
                float v1 = acc[mi][ni][h*2+1] + b1v;
                if (EPI == 4) {
                    float2 rr = *reinterpret_cast<const float2*>(res + (size_t)m * ldc + c0);
                    v0 += rr.x; v1 += rr.y;
                }
                if (EPI == 5) {
                    __half2 rr = *reinterpret_cast<const __half2*>(resh + (size_t)m * ldc + c0);
                    float2 fr = __half22float2(rr);
                    v0 += fr.x; v1 += fr.y;
                }
                if (EPI == 2) {
                    v0 = 0.5f * v0 * (1.0f + erff(v0 * 0.70710678118654752f));
                    v1 = 0.5f * v1 * (1.0f + erff(v1 * 0.70710678118654752f));
                }
                if (EPI == 2 || EPI == 3 || EPI == 4) {
                    *reinterpret_cast<__half2*>(Ch + (size_t)m * ldc + c0) =
                        __floats2half2_rn(v0, v1);
                } else {
                    *reinterpret_cast<float2*>(Cf + (size_t)m * ldc + c0) =
                        make_float2(v0, v1);
                }
            }
        }
    }
}

template<int EPI>
__global__ __launch_bounds__(256, 2) void mma_gemm(
    const __half* __restrict__ A, const __half* __restrict__ B,
    const float* __restrict__ bias, const float* __restrict__ res,
    const __half* __restrict__ resh,
    float* __restrict__ Cf, __half* __restrict__ Ch,
    int K, int ldc, int Ncols)
{
    extern __shared__ __half sm[];
    gemm_body<EPI>(A, B, bias, res, resh, Cf, Ch, K, ldc, Ncols,
                   blockIdx.y * 128, blockIdx.x * 128, sm);
}

// fused pair: value GEMM (768 CTAs) + offset/attention GEMM (256 CTAs)
__global__ __launch_bounds__(256, 2) void gemm_pair_kernel(
    const __half* __restrict__ xf, const __half* __restrict__ wvt,
    const float* __restrict__ bv, __half* __restrict__ val,
    const __half* __restrict__ xq, const __half* __restrict__ wct,
    const float* __restrict__ bcomb, float* __restrict__ offatt)
{
    extern __shared__ __half sm[];
    int t = blockIdx.x;
    if (t < 768) {
        gemm_body<3>(xf, wvt, bv, nullptr, nullptr, nullptr, val,
                     CC, CC, CC, (t / 6) * 128, (t % 6) * 128, sm);
    } else {
        int t2 = t - 768;
        gemm_body<0>(xq, wct, bcomb, nullptr, nullptr, offatt, nullptr,
                     CC, 192, 144, (t2 / 2) * 128, (t2 % 2) * 128, sm);
    }
}

// ---------------- sampling: one warp per (bq,head), half2 lanes ----------------
__global__ __launch_bounds__(256) void sample_kernel(
    const __half* __restrict__ value,
    const float* __restrict__ refp,
    const float* __restrict__ offatt,
    __half* __restrict__ oh)
{
    int gid = blockIdx.x * 8 + (threadIdx.x >> 5);
    int lane = threadIdx.x & 31;
    int head = gid % NHH;
    int bq   = gid / NHH;
    int b    = bq / LQ;

    const float* rp = refp + (size_t)bq * 2;
    float rx = rp[0], ry = rp[1];
    const float* op = offatt + (size_t)bq * 192 + head * 8;
    const float* lp = offatt + (size_t)bq * 192 + 96 + head * 4;

    float l0 = lp[0], l1 = lp[1], l2 = lp[2], l3 = lp[3];
    float mx = fmaxf(fmaxf(l0, l1), fmaxf(l2, l3));
    float e0 = expf(l0 - mx), e1 = expf(l1 - mx), e2 = expf(l2 - mx), e3 = expf(l3 - mx);
    float inv = 1.0f / (e0 + e1 + e2 + e3);
    float wsm[4] = {e0 * inv, e1 * inv, e2 * inv, e3 * inv};

    const __half* vb = value + (size_t)b * (HH * WW) * CC + head * DH + lane * 2;
    float a0 = 0.f, a1 = 0.f;
    #pragma unroll
    for (int p = 0; p < 4; p++) {
        float x = rx * (float)WW + op[p*2+0] - 0.5f;
        float y = ry * (float)HH + op[p*2+1] - 0.5f;
        float x0f = floorf(x), y0f = floorf(y);
        int   x0 = (int)x0f,  y0 = (int)y0f;
        float wx1 = x - x0f, wy1 = y - y0f;
        float wx0 = 1.f - wx1, wy0 = 1.f - wy1;
        float s0 = 0.f, s1 = 0.f;
        #pragma unroll
        for (int cc = 0; cc < 4; cc++) {
            int xi = x0 + (cc & 1);
            int yi = y0 + (cc >> 1);
            float w = ((cc & 1) ? wx1 : wx0) * ((cc >> 1) ? wy1 : wy0);
            if (xi >= 0 && xi < WW && yi >= 0 && yi < HH) {
                __half2 hv = *reinterpret_cast<const __half2*>(vb + (size_t)(yi * WW + xi) * CC);
                float2 fv = __half22float2(hv);
                s0 += w * fv.x;
                s1 += w * fv.y;
            }
        }
        a0 += wsm[p] * s0;
        a1 += wsm[p] * s1;
    }
    *reinterpret_cast<__half2*>(oh + (size_t)bq * CC + head * DH + lane * 2) =
        __floats2half2_rn(a0, a1);
}

// ---------------- launch ----------------
extern "C" void kernel_launch(void* const* d_in, const int* in_sizes, int n_in,
                              void* d_out, int out_size)
{
    const float* query = (const float*)d_in[0];
    const float* refp  = (const float*)d_in[1];
    const float* feat  = (const float*)d_in[2];
    int p = n_in - 18;
    const float* qn_g  = (const float*)d_in[p + 0];
    const float* qn_b  = (const float*)d_in[p + 1];
    const float* fn_g  = (const float*)d_in[p + 2];
    const float* fn_b  = (const float*)d_in[p + 3];
    const float* Wv    = (const float*)d_in[p + 4];
    const float* bv    = (const float*)d_in[p + 5];
    const float* Woff  = (const float*)d_in[p + 6];
    const float* boff  = (const float*)d_in[p + 7];
    const float* Watt  = (const float*)d_in[p + 8];
    const float* batt  = (const float*)d_in[p + 9];
    const float* Wout  = (const float*)d_in[p + 10];
    const float* bout  = (const float*)d_in[p + 11];
    const float* ffn_g = (const float*)d_in[p + 12];
    const float* ffn_b = (const float*)d_in[p + 13];
    const float* W1    = (const float*)d_in[p + 14];
    const float* b1    = (const float*)d_in[p + 15];
    const float* W2    = (const float*)d_in[p + 16];
    const float* b2    = (const float*)d_in[p + 17];
    float* out = (float*)d_out;

    __half *xf, *xq, *val, *s, *hmid, *out16;
    __half *wvt, *wot, *wct, *w1t, *w2t;
    float *offatt, *bcomb, *b1p;
    cudaGetSymbolAddress((void**)&xf, g_xf);
    cudaGetSymbolAddress((void**)&xq, g_xq);
    cudaGetSymbolAddress((void**)&val, g_value);
    cudaGetSymbolAddress((void**)&s, g_s);
    cudaGetSymbolAddress((void**)&hmid, g_hmid);
    cudaGetSymbolAddress((void**)&out16, g_out16);
    cudaGetSymbolAddress((void**)&wvt, g_wvt);
    cudaGetSymbolAddress((void**)&wot, g_wot);
    cudaGetSymbolAddress((void**)&wct, g_wct);
    cudaGetSymbolAddress((void**)&w1t, g_w1t);
    cudaGetSymbolAddress((void**)&w2t, g_w2t);
    cudaGetSymbolAddress((void**)&offatt, g_offatt);
    cudaGetSymbolAddress((void**)&bcomb, g_bcomb);
    cudaGetSymbolAddress((void**)&b1p, g_b1p);

    const int SMEM_GEMM = 3 * 2 * 128 * SSTR * 2;   // 110592 B (3-stage) -> 2 CTAs/SM
    cudaFuncSetAttribute(mma_gemm<4>, cudaFuncAttributeMaxDynamicSharedMemorySize, SMEM_GEMM);
    cudaFuncSetAttribute(mma_gemm<2>, cudaFuncAttributeMaxDynamicSharedMemorySize, SMEM_GEMM);
    cudaFuncSetAttribute(mma_gemm<5>, cudaFuncAttributeMaxDynamicSharedMemorySize, SMEM_GEMM);
    cudaFuncSetAttribute(gemm_pair_kernel, cudaFuncAttributeMaxDynamicSharedMemorySize, SMEM_GEMM);

    // 1. fused prep: coalesced weight transpose + LN(feat) + LN(query), warp-per-row
    prep_kernel<<<409 + 4096, 256>>>(feat, query, fn_g, fn_b, qn_g, qn_b, xf, xq,
        Wv, Wout, Woff, Watt, W1, W2, wvt, wot, wct, w1t, w2t,
        boff, batt, b1, bcomb, b1p);

    // 2. fused GEMM pair: value + offsets/logits
    gemm_pair_kernel<<<1024, 256, SMEM_GEMM>>>(xf, wvt, bv, val, xq, wct, bcomb, offatt);

    // 3. softmax + bilinear sampling (warp per (bq,head), half2 lanes)
    sample_kernel<<<MROWS * NHH / 8, 256>>>(val, refp, offatt, s);

    // 4. out16 = fp16(query + samp @ Wout + bout)
    mma_gemm<4><<<dim3(6, 128), 256, SMEM_GEMM>>>(s, wot, bout, query, nullptr,
        nullptr, out16, CC, CC, CC);

    // 5. FFN
    ln_h_kernel<<<MROWS / 8, 256>>>(out16, ffn_g, ffn_b, xf);
    mma_gemm<2><<<dim3(2, 128), 256, SMEM_GEMM>>>(xf, w1t, b1p, nullptr, nullptr,
        nullptr, hmid, CC, HID, HID);
    // 6. out = out16 + GELU(...) @ W2 + b2   (fp32 final)
    mma_gemm<5><<<dim3(6, 128), 256, SMEM_GEMM>>>(hmid, w2t, b2, nullptr, out16,
        out, nullptr, HID, CC, CC);
}